// round 1
// baseline (speedup 1.0000x reference)
#include <cuda_runtime.h>
#include <cuda_bf16.h>
#include <math.h>

#define B_   4
#define T_   32
#define N_   370
#define E_   11840
#define E2_  (E_ + N_)       // 12210
#define G_   128             // B*T
#define H_   64
#define GN   (G_ * N_)       // 47360
#define NH   (N_ * H_)       // 23680

// ---------------- scratch (device globals; no allocation allowed) ----------------
__device__ float d_h[GN * H_];          // node features between layers
__device__ float d_bufA[GN * H_];       // hw / gh
__device__ float d_bufB[GN * H_];       // GCN output g
__device__ float d_asrc[GN * 4];
__device__ float d_adst[GN * 4];
__device__ float d_gnorm[E2_];
__device__ int   d_csr_ptr[N_ + 1];
__device__ int   d_csr_eid[E2_];
__device__ float d_xt0[B_ * N_ * H_ * T_];
__device__ float d_xt1[B_ * N_ * H_ * T_];
__device__ float d_part[N_ * G_ * 256]; // split-K partials for MLP1 (48.5 MB)
__device__ float d_hid[G_ * 256];

__device__ __forceinline__ float gelu_f(float x) {
    return 0.5f * x * (1.0f + erff(x * 0.70710678118654752f));
}

// ---------------- prep: degrees, gnorm, deterministic CSR ----------------
__global__ void k_prep(const int* __restrict__ ei, const float* __restrict__ ew) {
    __shared__ float dis_s[N_];
    __shared__ int   cnt_s[N_];
    __shared__ int   ptr_s[N_ + 1];
    int t = threadIdx.x;
    const int* dsts = ei + E_;
    if (t < N_) {
        float deg = 1.0f;   // self-loop weight 1
        int   c   = 1;
        for (int e = 0; e < E_; e++) {
            if (dsts[e] == t) { deg += ew[e]; c++; }
        }
        dis_s[t] = rsqrtf(deg);
        cnt_s[t] = c;
    }
    __syncthreads();
    for (int e = t; e < E2_; e += blockDim.x) {
        float gn;
        if (e < E_) gn = dis_s[ei[e]] * ew[e] * dis_s[ei[E_ + e]];
        else        { int n = e - E_; gn = dis_s[n] * dis_s[n]; }
        d_gnorm[e] = gn;
    }
    if (t == 0) {
        int p = 0;
        for (int n = 0; n < N_; n++) { ptr_s[n] = p; p += cnt_s[n]; }
        ptr_s[N_] = p;
    }
    __syncthreads();
    if (t <= N_) d_csr_ptr[t] = ptr_s[t];
    if (t < N_) {
        int p = ptr_s[t];
        for (int e = 0; e < E_; e++)
            if (dsts[e] == t) d_csr_eid[p++] = e;
        d_csr_eid[p] = E_ + t;   // self-loop last (fixed, deterministic order)
    }
}

// ---------------- 64x64 GEMM: out[R,64] = in[R,64] @ W[64,64] ----------------
__global__ void k_gemm64(const float* __restrict__ in, const float* __restrict__ W,
                         float* __restrict__ out, int R) {
    __shared__ float Ws[64 * 64];
    __shared__ float Xs[16 * 64];
    int t = threadIdx.x;
    for (int i = t; i < 4096; i += 256) Ws[i] = W[i];
    int r0 = blockIdx.x * 16;
    for (int i = t; i < 1024; i += 256) {
        int r = i >> 6, k = i & 63;
        int rr = r0 + r;
        Xs[i] = (rr < R) ? in[(size_t)rr * 64 + k] : 0.0f;
    }
    __syncthreads();
    int c = t & 63, rs = t >> 6;
    float acc0 = 0.f, acc1 = 0.f, acc2 = 0.f, acc3 = 0.f;
    #pragma unroll 8
    for (int k = 0; k < 64; k++) {
        float w = Ws[k * 64 + c];
        acc0 += Xs[(rs     ) * 64 + k] * w;
        acc1 += Xs[(rs +  4) * 64 + k] * w;
        acc2 += Xs[(rs +  8) * 64 + k] * w;
        acc3 += Xs[(rs + 12) * 64 + k] * w;
    }
    if (r0 + rs      < R) out[(size_t)(r0 + rs     ) * 64 + c] = acc0;
    if (r0 + rs +  4 < R) out[(size_t)(r0 + rs +  4) * 64 + c] = acc1;
    if (r0 + rs +  8 < R) out[(size_t)(r0 + rs +  8) * 64 + c] = acc2;
    if (r0 + rs + 12 < R) out[(size_t)(r0 + rs + 12) * 64 + c] = acc3;
}

// ---------------- GCN aggregate + bias + GELU (gather over CSR) ----------------
__global__ void k_gcn_agg(const float* __restrict__ hw, const int* __restrict__ ei,
                          const float* __restrict__ bias, float* __restrict__ out) {
    int bid = blockIdx.x;
    int g = bid / N_, dst = bid % N_;
    int c = threadIdx.x;
    int p0 = d_csr_ptr[dst], p1 = d_csr_ptr[dst + 1];
    const float* base = hw + (size_t)g * NH;
    float acc = 0.0f;
    for (int p = p0; p < p1; p++) {
        int e = d_csr_eid[p];
        int s = (e < E_) ? ei[e] : (e - E_);
        acc += d_gnorm[e] * base[s * H_ + c];
    }
    out[(size_t)bid * H_ + c] = gelu_f(acc + bias[c]);
}

// ---------------- attention scores asrc/adst ----------------
__global__ void k_att(const float* __restrict__ gh, const float* __restrict__ aw_src,
                      const float* __restrict__ aw_dst) {
    int bid = blockIdx.x;
    int c = threadIdx.x;
    float v = gh[(size_t)bid * 64 + c];
    float a = v * aw_src[c];
    float b = v * aw_dst[c];
    #pragma unroll
    for (int off = 8; off > 0; off >>= 1) {
        a += __shfl_down_sync(0xffffffffu, a, off, 16);
        b += __shfl_down_sync(0xffffffffu, b, off, 16);
    }
    if ((c & 15) == 0) {
        int h = c >> 4;
        d_asrc[(size_t)bid * 4 + h] = a;
        d_adst[(size_t)bid * 4 + h] = b;
    }
}

// ------- GAT aggregate (edge softmax) + bias + residual + LayerNorm, fused -------
__global__ void k_gat(const float* __restrict__ gh, const int* __restrict__ ei,
                      const float* __restrict__ bias, const float* __restrict__ lng,
                      const float* __restrict__ lnb, const float* __restrict__ hin,
                      float* __restrict__ hout) {
    int bid = blockIdx.x;
    int g = bid / N_, dst = bid % N_;
    int c = threadIdx.x;
    int hh = c >> 4;
    int p0 = d_csr_ptr[dst], p1 = d_csr_ptr[dst + 1];
    const float* asr = d_asrc + (size_t)g * N_ * 4;
    float adst_h = d_adst[(size_t)bid * 4 + hh];

    // pass 1: max
    float m = -1e30f;
    for (int p = p0; p < p1; p++) {
        int e = d_csr_eid[p];
        int s = (e < E_) ? ei[e] : (e - E_);
        float a = asr[s * 4 + hh] + adst_h;
        a = fmaxf(a, 0.2f * a);   // leaky_relu(0.2)
        m = fmaxf(m, a);
    }
    // pass 2: denominator
    float den = 0.0f;
    for (int p = p0; p < p1; p++) {
        int e = d_csr_eid[p];
        int s = (e < E_) ? ei[e] : (e - E_);
        float a = asr[s * 4 + hh] + adst_h;
        a = fmaxf(a, 0.2f * a);
        den += expf(a - m);
    }
    float inv_den = 1.0f / den;
    // pass 3: weighted sum of messages
    float acc = 0.0f;
    const float* ghb = gh + (size_t)g * NH;
    for (int p = p0; p < p1; p++) {
        int e = d_csr_eid[p];
        int s = (e < E_) ? ei[e] : (e - E_);
        float a = asr[s * 4 + hh] + adst_h;
        a = fmaxf(a, 0.2f * a);
        float alpha = expf(a - m) * inv_den;
        acc += alpha * ghb[s * 64 + c];
    }
    float r = acc + bias[c] + hin[(size_t)bid * 64 + c];

    // LayerNorm across 64 channels (2 warps)
    float s1 = r, s2 = r * r;
    #pragma unroll
    for (int off = 16; off > 0; off >>= 1) {
        s1 += __shfl_down_sync(0xffffffffu, s1, off);
        s2 += __shfl_down_sync(0xffffffffu, s2, off);
    }
    __shared__ float red[4];
    if ((c & 31) == 0) { red[(c >> 5) * 2] = s1; red[(c >> 5) * 2 + 1] = s2; }
    __syncthreads();
    float tot  = red[0] + red[2];
    float tot2 = red[1] + red[3];
    float mu  = tot * (1.0f / 64.0f);
    float var = fmaxf(tot2 * (1.0f / 64.0f) - mu * mu, 0.0f);
    hout[(size_t)bid * 64 + c] = (r - mu) * rsqrtf(var + 1e-5f) * lng[c] + lnb[c];
}

// ---------------- transpose h (G,N,H) -> xt (B*N, H, T) ----------------
__global__ void k_trans(const float* __restrict__ h, float* __restrict__ xt) {
    int idx = blockIdx.x * blockDim.x + threadIdx.x;
    if (idx >= B_ * N_ * H_ * T_) return;
    int t = idx & 31;
    int c = (idx >> 5) & 63;
    int n = (idx / (32 * 64)) % N_;
    int b = idx / (32 * 64 * N_);
    xt[idx] = h[(((size_t)(b * T_ + t) * N_ + n) * H_) + c];
}

// ---------------- temporal conv: out = gelu(conv(in) + b) + in ----------------
__global__ void k_tconv(const float* __restrict__ in, float* __restrict__ out,
                        const float* __restrict__ W, const float* __restrict__ bias) {
    extern __shared__ float sm[];
    float* xs = sm;           // 2048: [64 ch][32 t]
    float* ws = sm + 2048;    // 20480: [o][i][k]
    int bn  = blockIdx.x;
    int tid = threadIdx.x;
    const float* ib = in + (size_t)bn * 2048;
    for (int i = tid; i < 2048; i += 256) xs[i] = ib[i];
    for (int i = tid; i < 20480; i += 256) ws[i] = W[i];
    __syncthreads();
    for (int idx = tid; idx < 2048; idx += 256) {
        int o = idx >> 5, t = idx & 31;
        float acc = bias[o];
        const float* wo = ws + o * 320;
        #pragma unroll 4
        for (int i = 0; i < 64; i++) {
            const float* wr = wo + i * 5;
            const float* xr = xs + i * 32;
            #pragma unroll
            for (int k = 0; k < 5; k++) {
                int tt = t + k - 2;
                if (tt >= 0 && tt < 32) acc += xr[tt] * wr[k];
            }
        }
        out[(size_t)bn * 2048 + idx] = gelu_f(acc) + xs[idx];
    }
}

// ------- MLP1 split-K: block per node n, partial C[128,256] over its 64 K-rows -------
#define ZS_STRIDE 65
__global__ void k_mlp1(const float* __restrict__ xt, const float* __restrict__ W1) {
    extern __shared__ float sm[];
    float* zs  = sm;                       // 128 * 65 (padded)
    float* w1s = sm + G_ * ZS_STRIDE;      // 64 * 256
    int n   = blockIdx.x;
    int tid = threadIdx.x;
    // load z slice: z[g, n*64+c] = xt[((b*N+n)*64+c)*32 + t], g = b*32 + t
    for (int i = tid; i < 8192; i += 256) {
        int b = i >> 11, c = (i >> 5) & 63, t = i & 31;
        int g = b * 32 + t;
        zs[g * ZS_STRIDE + c] = xt[(((size_t)(b * N_ + n)) * 64 + c) * 32 + t];
    }
    for (int i = tid; i < 16384; i += 256) {
        int k = i >> 8, o = i & 255;
        w1s[i] = W1[((size_t)(n * 64 + k)) * 256 + o];
    }
    __syncthreads();
    int o = tid;
    float* pb = d_part + (size_t)n * (G_ * 256);
    for (int g = 0; g < G_; g++) {
        float acc = 0.0f;
        const float* zr = zs + g * ZS_STRIDE;
        #pragma unroll 8
        for (int k = 0; k < 64; k++) acc += zr[k] * w1s[k * 256 + o];
        pb[g * 256 + o] = acc;
    }
}

// ---------------- reduce partials + bias + GELU ----------------
__global__ void k_red(const float* __restrict__ b1) {
    int idx = blockIdx.x * 256 + threadIdx.x;   // < 32768
    float acc = 0.0f;
    for (int nb = 0; nb < N_; nb++) acc += d_part[(size_t)nb * (G_ * 256) + idx];
    int o = idx & 255;
    d_hid[idx] = gelu_f(acc + b1[o]);
}

// ---------------- MLP2 ----------------
__global__ void k_mlp2(const float* __restrict__ W2, const float* __restrict__ b2,
                       float* __restrict__ out) {
    int g = blockIdx.x;
    int o = threadIdx.x;   // 64
    float acc = b2[o];
    const float* hr = d_hid + (size_t)g * 256;
    #pragma unroll 8
    for (int k = 0; k < 256; k++) acc += hr[k] * W2[k * 64 + o];
    out[(size_t)g * 64 + o] = acc;
}

// ---------------- host orchestration ----------------
extern "C" void kernel_launch(void* const* d_in, const int* in_sizes, int n_in,
                              void* d_out, int out_size) {
    const float* x       = (const float*)d_in[0];
    const int*   ei      = (const int*)  d_in[1];
    const float* ew      = (const float*)d_in[2];
    const float* W_gcn   = (const float*)d_in[3];
    const float* b_gcn   = (const float*)d_in[4];
    const float* W_gat   = (const float*)d_in[5];
    const float* att_src = (const float*)d_in[6];
    const float* att_dst = (const float*)d_in[7];
    const float* b_gat   = (const float*)d_in[8];
    const float* W_t     = (const float*)d_in[9];
    const float* b_t     = (const float*)d_in[10];
    const float* ln_g    = (const float*)d_in[11];
    const float* ln_b    = (const float*)d_in[12];
    const float* W1      = (const float*)d_in[13];
    const float* b1      = (const float*)d_in[14];
    const float* W2      = (const float*)d_in[15];
    const float* b2      = (const float*)d_in[16];
    float* out = (float*)d_out;

    const int tconv_smem = (2048 + 20480) * 4;                     // 90112
    const int mlp1_smem  = (G_ * ZS_STRIDE + 64 * 256) * 4;        // 98816
    cudaFuncSetAttribute(k_tconv, cudaFuncAttributeMaxDynamicSharedMemorySize, tconv_smem);
    cudaFuncSetAttribute(k_mlp1,  cudaFuncAttributeMaxDynamicSharedMemorySize, mlp1_smem);

    k_prep<<<1, 512>>>(ei, ew);

    const float* hin = x;
    for (int l = 0; l < 3; l++) {
        k_gemm64<<<GN / 16, 256>>>(hin, W_gcn + l * 4096, d_bufA, GN);
        k_gcn_agg<<<GN, 64>>>(d_bufA, ei, b_gcn + l * 64, d_bufB);
        k_gemm64<<<GN / 16, 256>>>(d_bufB, W_gat + l * 4096, d_bufA, GN);
        k_att<<<GN, 64>>>(d_bufA, att_src + l * 64, att_dst + l * 64);
        k_gat<<<GN, 64>>>(d_bufA, ei, b_gat + l * 64, ln_g + l * 64, ln_b + l * 64,
                          hin, d_h);
        hin = d_h;
    }

    int total = B_ * N_ * H_ * T_;
    k_trans<<<(total + 255) / 256, 256>>>(d_h, d_xt0);
    k_tconv<<<B_ * N_, 256, tconv_smem>>>(d_xt0, d_xt1, W_t + 0 * 20480, b_t + 0 * 64);
    k_tconv<<<B_ * N_, 256, tconv_smem>>>(d_xt1, d_xt0, W_t + 1 * 20480, b_t + 1 * 64);
    k_tconv<<<B_ * N_, 256, tconv_smem>>>(d_xt0, d_xt1, W_t + 2 * 20480, b_t + 2 * 64);

    k_mlp1<<<N_, 256, mlp1_smem>>>(d_xt1, W1);
    k_red<<<(G_ * 256) / 256, 256>>>(b1);
    k_mlp2<<<G_, 64>>>(W2, b2, out);
}

// round 2
// speedup vs baseline: 1.0791x; 1.0791x over previous
#include <cuda_runtime.h>
#include <cuda_bf16.h>
#include <math.h>

#define B_   4
#define T_   32
#define N_   370
#define E_   11840
#define E2_  (E_ + N_)       // 12210
#define G_   128             // B*T
#define H_   64
#define GN   (G_ * N_)       // 47360 = 740 * 64
#define NH   (N_ * H_)       // 23680
#define CHUNK_ 512
#define GAT_CAP 192

// ---------------- scratch (device globals) ----------------
__device__ float  d_h[GN * H_];
__device__ float  d_bufA[GN * H_];
__device__ float  d_bufB[GN * H_];
__device__ float  d_asrc[GN * 4];
__device__ float  d_adst[GN * 4];
__device__ int    d_csr_ptr[N_ + 1];
__device__ int    d_csr_eid[E2_];
__device__ float2 d_csr_sg[E2_];      // {src (bits), gnorm} in CSR order
__device__ int    d_cnt[CHUNK_ * N_];
__device__ float  d_xt0[B_ * N_ * H_ * T_];
__device__ float  d_xt1[B_ * N_ * H_ * T_];
__device__ float  d_part[N_ * G_ * 256];
__device__ float  d_hid[G_ * 256];

__device__ __forceinline__ float gelu_f(float x) {
    return 0.5f * x * (1.0f + erff(x * 0.70710678118654752f));
}

// ---------------- prep: deterministic parallel CSR + packed (src,gnorm) ----------------
__global__ void k_prep(const int* __restrict__ ei, const float* __restrict__ ew) {
    int t = threadIdx.x;                 // 512 threads, 1 block
    const int* srcs = ei;
    const int* dsts = ei + E_;
    const int EC = (E_ + CHUNK_ - 1) / CHUNK_;       // 24
    int e0 = t * EC;
    int e1 = min(e0 + EC, E_);
    __shared__ int   ptr_s[N_ + 1];
    __shared__ float dis_s[N_];

    // A: zero counts
    for (int i = t; i < CHUNK_ * N_; i += CHUNK_) d_cnt[i] = 0;
    __syncthreads();
    // B: per-chunk counts (own row, no atomics)
    for (int e = e0; e < e1; e++) d_cnt[t * N_ + dsts[e]]++;
    __syncthreads();
    // C: exclusive prefix over chunks per dst
    if (t < N_) {
        int run = 0;
        for (int c = 0; c < CHUNK_; c++) {
            int idx = c * N_ + t;
            int v = d_cnt[idx];
            d_cnt[idx] = run;
            run += v;
        }
        ptr_s[t] = run + 1;              // + self loop
    }
    __syncthreads();
    if (t == 0) {
        int p = 0;
        for (int n = 0; n < N_; n++) { int v = ptr_s[n]; ptr_s[n] = p; p += v; }
        ptr_s[N_] = p;                   // == E2_
    }
    __syncthreads();
    if (t <= N_) d_csr_ptr[t] = ptr_s[t];
    // D: stable fill (chunk order == edge order)
    for (int e = e0; e < e1; e++) {
        int d = dsts[e];
        int pos = ptr_s[d] + d_cnt[t * N_ + d]++;
        d_csr_eid[pos] = e;
    }
    __syncthreads();
    // self-loop last within each dst
    if (t < N_) d_csr_eid[ptr_s[t + 1] - 1] = E_ + t;
    __syncthreads();
    // E: deg (edge order) -> dis
    if (t < N_) {
        float deg = 1.0f;
        for (int p = ptr_s[t]; p < ptr_s[t + 1] - 1; p++) deg += ew[d_csr_eid[p]];
        dis_s[t] = rsqrtf(deg);
    }
    __syncthreads();
    // F: packed (src, gnorm) in CSR order
    if (t < N_) {
        float dd = dis_s[t];
        for (int p = ptr_s[t]; p < ptr_s[t + 1]; p++) {
            int e = d_csr_eid[p];
            int s; float gn;
            if (e < E_) { s = srcs[e]; gn = dis_s[s] * ew[e] * dd; }
            else        { s = t;       gn = dd * dd; }
            d_csr_sg[p] = make_float2(__int_as_float(s), gn);
        }
    }
}

// ---------------- 64x64 GEMM, 4x4 register tile per thread ----------------
__global__ void k_gemm64(const float* __restrict__ in, const float* __restrict__ W,
                         float* __restrict__ out) {
    __shared__ __align__(16) float XsT[64 * 68];   // [k][r], stride 68
    __shared__ __align__(16) float Ws[64 * 64];    // [k][c]
    int tid = threadIdx.x;
    int r0 = blockIdx.x * 64;
    for (int i = tid; i < 4096; i += 256) Ws[i] = W[i];
    for (int i = tid; i < 4096; i += 256) {
        int r = i >> 6, k = i & 63;
        XsT[k * 68 + r] = in[(size_t)(r0 + r) * 64 + k];
    }
    __syncthreads();
    int tx = tid & 15, ty = tid >> 4;
    int c0 = tx * 4, rr = ty * 4;
    float acc[4][4] = {};
    #pragma unroll 4
    for (int k = 0; k < 64; k++) {
        float4 a4 = *(const float4*)&XsT[k * 68 + rr];
        float4 b4 = *(const float4*)&Ws[k * 64 + c0];
        float a[4] = {a4.x, a4.y, a4.z, a4.w};
        float b[4] = {b4.x, b4.y, b4.z, b4.w};
        #pragma unroll
        for (int i = 0; i < 4; i++)
            #pragma unroll
            for (int j = 0; j < 4; j++)
                acc[i][j] = fmaf(a[i], b[j], acc[i][j]);
    }
    #pragma unroll
    for (int i = 0; i < 4; i++) {
        float4 v = make_float4(acc[i][0], acc[i][1], acc[i][2], acc[i][3]);
        *(float4*)&out[(size_t)(r0 + rr + i) * 64 + c0] = v;
    }
}

// ---------------- GCN aggregate + bias + GELU ----------------
__global__ void k_gcn_agg(const float* __restrict__ hw, const float* __restrict__ bias,
                          float* __restrict__ out) {
    int bid = blockIdx.x;
    int g = bid / N_, dstn = bid % N_;
    int c = threadIdx.x;
    int p0 = d_csr_ptr[dstn], p1 = d_csr_ptr[dstn + 1];
    const float* base = hw + (size_t)g * NH;
    float a0 = 0.f, a1 = 0.f, a2 = 0.f, a3 = 0.f;
    int p = p0;
    for (; p + 4 <= p1; p += 4) {
        float2 e0 = d_csr_sg[p];
        float2 e1 = d_csr_sg[p + 1];
        float2 e2 = d_csr_sg[p + 2];
        float2 e3 = d_csr_sg[p + 3];
        a0 = fmaf(e0.y, base[__float_as_int(e0.x) * 64 + c], a0);
        a1 = fmaf(e1.y, base[__float_as_int(e1.x) * 64 + c], a1);
        a2 = fmaf(e2.y, base[__float_as_int(e2.x) * 64 + c], a2);
        a3 = fmaf(e3.y, base[__float_as_int(e3.x) * 64 + c], a3);
    }
    for (; p < p1; p++) {
        float2 e = d_csr_sg[p];
        a0 = fmaf(e.y, base[__float_as_int(e.x) * 64 + c], a0);
    }
    float acc = (a0 + a1) + (a2 + a3) + bias[c];
    out[(size_t)bid * 64 + c] = gelu_f(acc);
}

// ---------------- attention scores asrc/adst ----------------
__global__ void k_att(const float* __restrict__ gh, const float* __restrict__ aw_src,
                      const float* __restrict__ aw_dst) {
    int bid = blockIdx.x;
    int c = threadIdx.x;
    float v = gh[(size_t)bid * 64 + c];
    float a = v * aw_src[c];
    float b = v * aw_dst[c];
    #pragma unroll
    for (int off = 8; off > 0; off >>= 1) {
        a += __shfl_down_sync(0xffffffffu, a, off, 16);
        b += __shfl_down_sync(0xffffffffu, b, off, 16);
    }
    if ((c & 15) == 0) {
        int h = c >> 4;
        d_asrc[(size_t)bid * 4 + h] = a;
        d_adst[(size_t)bid * 4 + h] = b;
    }
}

// ------- GAT: edge softmax in smem + gather + bias + residual + LayerNorm -------
__global__ void k_gat(const float* __restrict__ gh, const float* __restrict__ bias,
                      const float* __restrict__ lng, const float* __restrict__ lnb,
                      const float* __restrict__ hin, float* __restrict__ hout) {
    __shared__ int   s_src[GAT_CAP];
    __shared__ float s_a[GAT_CAP * 4];
    __shared__ float s_red[8];
    __shared__ float s_m[4], s_d[4];
    __shared__ float lnred[4];
    int bid = blockIdx.x;
    int g = bid / N_, dstn = bid % N_;
    int tid = threadIdx.x;
    int p0 = d_csr_ptr[dstn], p1 = d_csr_ptr[dstn + 1];
    int deg = p1 - p0;
    const float* asr = d_asrc + (size_t)g * (N_ * 4);
    float4 ad = *(const float4*)&d_adst[(size_t)bid * 4];
    int c = tid, hh = c >> 4;
    const float* ghb = gh + (size_t)g * NH;
    float accv;

    if (deg <= GAT_CAP) {
        float m0 = -1e30f, m1 = -1e30f, m2 = -1e30f, m3 = -1e30f;
        for (int j = tid; j < deg; j += 64) {
            float2 sg = d_csr_sg[p0 + j];
            int s = __float_as_int(sg.x);
            float4 av = *(const float4*)&asr[s * 4];
            float a0 = av.x + ad.x, a1 = av.y + ad.y, a2 = av.z + ad.z, a3 = av.w + ad.w;
            a0 = fmaxf(a0, 0.2f * a0); a1 = fmaxf(a1, 0.2f * a1);
            a2 = fmaxf(a2, 0.2f * a2); a3 = fmaxf(a3, 0.2f * a3);
            s_src[j] = s;
            s_a[j * 4 + 0] = a0; s_a[j * 4 + 1] = a1;
            s_a[j * 4 + 2] = a2; s_a[j * 4 + 3] = a3;
            m0 = fmaxf(m0, a0); m1 = fmaxf(m1, a1);
            m2 = fmaxf(m2, a2); m3 = fmaxf(m3, a3);
        }
        #pragma unroll
        for (int off = 16; off > 0; off >>= 1) {
            m0 = fmaxf(m0, __shfl_xor_sync(0xffffffffu, m0, off));
            m1 = fmaxf(m1, __shfl_xor_sync(0xffffffffu, m1, off));
            m2 = fmaxf(m2, __shfl_xor_sync(0xffffffffu, m2, off));
            m3 = fmaxf(m3, __shfl_xor_sync(0xffffffffu, m3, off));
        }
        if ((tid & 31) == 0) {
            int w = tid >> 5;
            s_red[w * 4 + 0] = m0; s_red[w * 4 + 1] = m1;
            s_red[w * 4 + 2] = m2; s_red[w * 4 + 3] = m3;
        }
        __syncthreads();
        if (tid < 4) s_m[tid] = fmaxf(s_red[tid], s_red[4 + tid]);
        __syncthreads();
        float M0 = s_m[0], M1 = s_m[1], M2 = s_m[2], M3 = s_m[3];
        float d0 = 0.f, d1 = 0.f, d2 = 0.f, d3 = 0.f;
        for (int j = tid; j < deg; j += 64) {
            d0 += expf(s_a[j * 4 + 0] - M0);
            d1 += expf(s_a[j * 4 + 1] - M1);
            d2 += expf(s_a[j * 4 + 2] - M2);
            d3 += expf(s_a[j * 4 + 3] - M3);
        }
        #pragma unroll
        for (int off = 16; off > 0; off >>= 1) {
            d0 += __shfl_xor_sync(0xffffffffu, d0, off);
            d1 += __shfl_xor_sync(0xffffffffu, d1, off);
            d2 += __shfl_xor_sync(0xffffffffu, d2, off);
            d3 += __shfl_xor_sync(0xffffffffu, d3, off);
        }
        __syncthreads();
        if ((tid & 31) == 0) {
            int w = tid >> 5;
            s_red[w * 4 + 0] = d0; s_red[w * 4 + 1] = d1;
            s_red[w * 4 + 2] = d2; s_red[w * 4 + 3] = d3;
        }
        __syncthreads();
        if (tid < 4) s_d[tid] = 1.0f / (s_red[tid] + s_red[4 + tid]);
        __syncthreads();
        float I0 = s_d[0], I1 = s_d[1], I2 = s_d[2], I3 = s_d[3];
        // overwrite s_a with alpha
        for (int j = tid; j < deg; j += 64) {
            s_a[j * 4 + 0] = expf(s_a[j * 4 + 0] - M0) * I0;
            s_a[j * 4 + 1] = expf(s_a[j * 4 + 1] - M1) * I1;
            s_a[j * 4 + 2] = expf(s_a[j * 4 + 2] - M2) * I2;
            s_a[j * 4 + 3] = expf(s_a[j * 4 + 3] - M3) * I3;
        }
        __syncthreads();
        float a0 = 0.f, a1 = 0.f, a2 = 0.f, a3 = 0.f;
        int j = 0;
        for (; j + 4 <= deg; j += 4) {
            a0 = fmaf(s_a[(j + 0) * 4 + hh], ghb[s_src[j + 0] * 64 + c], a0);
            a1 = fmaf(s_a[(j + 1) * 4 + hh], ghb[s_src[j + 1] * 64 + c], a1);
            a2 = fmaf(s_a[(j + 2) * 4 + hh], ghb[s_src[j + 2] * 64 + c], a2);
            a3 = fmaf(s_a[(j + 3) * 4 + hh], ghb[s_src[j + 3] * 64 + c], a3);
        }
        for (; j < deg; j++)
            a0 = fmaf(s_a[j * 4 + hh], ghb[s_src[j] * 64 + c], a0);
        accv = (a0 + a1) + (a2 + a3);
    } else {
        // fallback (deg > CAP): 3-pass global recompute
        float adh = (hh == 0) ? ad.x : (hh == 1) ? ad.y : (hh == 2) ? ad.z : ad.w;
        float m = -1e30f;
        for (int p = p0; p < p1; p++) {
            float2 sg = d_csr_sg[p];
            float a = asr[__float_as_int(sg.x) * 4 + hh] + adh;
            a = fmaxf(a, 0.2f * a);
            m = fmaxf(m, a);
        }
        float den = 0.f;
        for (int p = p0; p < p1; p++) {
            float2 sg = d_csr_sg[p];
            float a = asr[__float_as_int(sg.x) * 4 + hh] + adh;
            a = fmaxf(a, 0.2f * a);
            den += expf(a - m);
        }
        float inv = 1.0f / den;
        float acc = 0.f;
        for (int p = p0; p < p1; p++) {
            float2 sg = d_csr_sg[p];
            int s = __float_as_int(sg.x);
            float a = asr[s * 4 + hh] + adh;
            a = fmaxf(a, 0.2f * a);
            acc = fmaf(expf(a - m) * inv, ghb[s * 64 + c], acc);
        }
        accv = acc;
    }

    float r = accv + bias[c] + hin[(size_t)bid * 64 + c];
    float s1 = r, s2 = r * r;
    #pragma unroll
    for (int off = 16; off > 0; off >>= 1) {
        s1 += __shfl_xor_sync(0xffffffffu, s1, off);
        s2 += __shfl_xor_sync(0xffffffffu, s2, off);
    }
    __syncthreads();
    if ((c & 31) == 0) { lnred[(c >> 5) * 2] = s1; lnred[(c >> 5) * 2 + 1] = s2; }
    __syncthreads();
    float tot = lnred[0] + lnred[2];
    float tot2 = lnred[1] + lnred[3];
    float mu = tot * (1.0f / 64.0f);
    float var = fmaxf(tot2 * (1.0f / 64.0f) - mu * mu, 0.0f);
    hout[(size_t)bid * 64 + c] = (r - mu) * rsqrtf(var + 1e-5f) * lng[c] + lnb[c];
}

// ---------------- temporal conv: out = gelu(conv(in)+b) + in, 4 bn per block ----------------
#define WS_FLOATS (320 * 65)                 // 20800
#define XS_STRIDE 40
#define XS_PER_BN (64 * XS_STRIDE)           // 2560
#define TCONV_SMEM ((WS_FLOATS + 4 * XS_PER_BN) * 4)

__global__ void k_tconv(const float* __restrict__ in, float* __restrict__ out,
                        const float* __restrict__ W, const float* __restrict__ bias,
                        int from_h) {
    extern __shared__ __align__(16) float sm[];
    float* ws = sm;                          // [r=i*5+k][o], stride 65
    float* xs = sm + WS_FLOATS;              // 4 bn x 64 i x 40 (halo at [0..3],[36..39])
    int tid = threadIdx.x;
    int bn0 = blockIdx.x * 4;

    for (int i = tid; i < 20480; i += 256) {
        int o = i / 320, r = i % 320;
        ws[r * 65 + o] = W[i];
    }
    for (int i = tid; i < 4 * XS_PER_BN; i += 256) xs[i] = 0.0f;
    __syncthreads();
    for (int idx = tid; idx < 4 * 2048; idx += 256) {
        int bnL = idx >> 11;
        int r = idx & 2047;
        int bn = bn0 + bnL;
        float v;
        int i2, tt;
        if (from_h) {
            tt = r >> 6; i2 = r & 63;
            int b = bn / N_, n = bn % N_;
            v = in[(((size_t)(b * 32 + tt) * N_) + n) * 64 + i2];
        } else {
            i2 = r >> 5; tt = r & 31;
            v = in[(size_t)bn * 2048 + r];
        }
        xs[bnL * XS_PER_BN + i2 * XS_STRIDE + 4 + tt] = v;
    }
    __syncthreads();

    int o = tid & 63, bnL = tid >> 6;
    const float* xr = xs + bnL * XS_PER_BN;
    float acc[32];
    float bo = bias[o];
    #pragma unroll
    for (int t = 0; t < 32; t++) acc[t] = bo;
    for (int i = 0; i < 64; i++) {
        float xw[40];
        #pragma unroll
        for (int q = 0; q < 10; q++)
            *(float4*)&xw[q * 4] = *(const float4*)&xr[i * XS_STRIDE + q * 4];
        float w0 = ws[(i * 5 + 0) * 65 + o];
        float w1 = ws[(i * 5 + 1) * 65 + o];
        float w2 = ws[(i * 5 + 2) * 65 + o];
        float w3 = ws[(i * 5 + 3) * 65 + o];
        float w4 = ws[(i * 5 + 4) * 65 + o];
        #pragma unroll
        for (int t = 0; t < 32; t++) {
            float a = acc[t];
            a = fmaf(xw[t + 2], w0, a);
            a = fmaf(xw[t + 3], w1, a);
            a = fmaf(xw[t + 4], w2, a);
            a = fmaf(xw[t + 5], w3, a);
            a = fmaf(xw[t + 6], w4, a);
            acc[t] = a;
        }
    }
    int bn = bn0 + bnL;
    float* ob = out + (size_t)bn * 2048 + o * 32;
    #pragma unroll
    for (int t = 0; t < 32; t++) {
        float xin = xr[o * XS_STRIDE + 4 + t];
        ob[t] = gelu_f(acc[t]) + xin;
    }
}

// ---------------- MLP1 split-K over nodes: 4g x 8o register tiles ----------------
#define ZS_STRIDE 65
#define MLP1_SMEM ((G_ * ZS_STRIDE + 64 * 256) * 4)
__global__ void k_mlp1(const float* __restrict__ xt, const float* __restrict__ W1) {
    extern __shared__ __align__(16) float sm[];
    float* zs  = sm;                       // [g][k], stride 65
    float* w1s = sm + G_ * ZS_STRIDE;      // [k][o]
    int n = blockIdx.x, tid = threadIdx.x;
    for (int i = tid; i < 8192; i += 256) {
        int b = i >> 11, c = (i >> 5) & 63, t = i & 31;
        zs[(b * 32 + t) * ZS_STRIDE + c] = xt[(((size_t)(b * N_ + n)) * 64 + c) * 32 + t];
    }
    for (int i = tid; i < 16384; i += 256)
        w1s[i] = W1[(size_t)n * 16384 + i];
    __syncthreads();
    int ow = tid & 31, gw = tid >> 5;
    int o0 = ow * 8;
    float* pb = d_part + (size_t)n * (G_ * 256);
    for (int pass = 0; pass < 4; pass++) {
        int g0 = pass * 32 + gw * 4;
        float acc[4][8] = {};
        #pragma unroll 4
        for (int k = 0; k < 64; k++) {
            float4 wa = *(const float4*)&w1s[k * 256 + o0];
            float4 wb = *(const float4*)&w1s[k * 256 + o0 + 4];
            float w[8] = {wa.x, wa.y, wa.z, wa.w, wb.x, wb.y, wb.z, wb.w};
            float z[4];
            #pragma unroll
            for (int j = 0; j < 4; j++) z[j] = zs[(g0 + j) * ZS_STRIDE + k];
            #pragma unroll
            for (int j = 0; j < 4; j++)
                #pragma unroll
                for (int q = 0; q < 8; q++)
                    acc[j][q] = fmaf(z[j], w[q], acc[j][q]);
        }
        #pragma unroll
        for (int j = 0; j < 4; j++) {
            *(float4*)&pb[(g0 + j) * 256 + o0]     = make_float4(acc[j][0], acc[j][1], acc[j][2], acc[j][3]);
            *(float4*)&pb[(g0 + j) * 256 + o0 + 4] = make_float4(acc[j][4], acc[j][5], acc[j][6], acc[j][7]);
        }
    }
}

// ---------------- reduce partials + bias + GELU ----------------
__global__ void k_red(const float* __restrict__ b1) {
    int idx = blockIdx.x * 256 + threadIdx.x;
    float a0 = 0.f, a1 = 0.f;
    int nb = 0;
    for (; nb + 2 <= N_; nb += 2) {
        a0 += d_part[(size_t)nb * (G_ * 256) + idx];
        a1 += d_part[(size_t)(nb + 1) * (G_ * 256) + idx];
    }
    for (; nb < N_; nb++) a0 += d_part[(size_t)nb * (G_ * 256) + idx];
    int o = idx & 255;
    d_hid[idx] = gelu_f(a0 + a1 + b1[o]);
}

// ---------------- MLP2 ----------------
__global__ void k_mlp2(const float* __restrict__ W2, const float* __restrict__ b2,
                       float* __restrict__ out) {
    int g = blockIdx.x;
    int o = threadIdx.x;
    float acc = b2[o];
    const float* hr = d_hid + (size_t)g * 256;
    #pragma unroll 8
    for (int k = 0; k < 256; k++) acc = fmaf(hr[k], W2[k * 64 + o], acc);
    out[(size_t)g * 64 + o] = acc;
}

// ---------------- host orchestration ----------------
extern "C" void kernel_launch(void* const* d_in, const int* in_sizes, int n_in,
                              void* d_out, int out_size) {
    const float* x       = (const float*)d_in[0];
    const int*   ei      = (const int*)  d_in[1];
    const float* ew      = (const float*)d_in[2];
    const float* W_gcn   = (const float*)d_in[3];
    const float* b_gcn   = (const float*)d_in[4];
    const float* W_gat   = (const float*)d_in[5];
    const float* att_src = (const float*)d_in[6];
    const float* att_dst = (const float*)d_in[7];
    const float* b_gat   = (const float*)d_in[8];
    const float* W_t     = (const float*)d_in[9];
    const float* b_t     = (const float*)d_in[10];
    const float* ln_g    = (const float*)d_in[11];
    const float* ln_b    = (const float*)d_in[12];
    const float* W1      = (const float*)d_in[13];
    const float* b1      = (const float*)d_in[14];
    const float* W2      = (const float*)d_in[15];
    const float* b2      = (const float*)d_in[16];
    float* out = (float*)d_out;

    cudaFuncSetAttribute(k_tconv, cudaFuncAttributeMaxDynamicSharedMemorySize, TCONV_SMEM);
    cudaFuncSetAttribute(k_mlp1,  cudaFuncAttributeMaxDynamicSharedMemorySize, MLP1_SMEM);

    k_prep<<<1, CHUNK_>>>(ei, ew);

    const float* hin = x;
    for (int l = 0; l < 3; l++) {
        k_gemm64<<<GN / 64, 256>>>(hin, W_gcn + l * 4096, d_bufA);
        k_gcn_agg<<<GN, 64>>>(d_bufA, b_gcn + l * 64, d_bufB);
        k_gemm64<<<GN / 64, 256>>>(d_bufB, W_gat + l * 4096, d_bufA);
        k_att<<<GN, 64>>>(d_bufA, att_src + l * 64, att_dst + l * 64);
        k_gat<<<GN, 64>>>(d_bufA, b_gat + l * 64, ln_g + l * 64, ln_b + l * 64,
                          hin, d_h);
        hin = d_h;
    }

    // temporal convs (layer 1 reads d_h directly, transposing on the fly)
    k_tconv<<<(B_ * N_) / 4, 256, TCONV_SMEM>>>(d_h,   d_xt0, W_t + 0 * 20480, b_t + 0 * 64, 1);
    k_tconv<<<(B_ * N_) / 4, 256, TCONV_SMEM>>>(d_xt0, d_xt1, W_t + 1 * 20480, b_t + 1 * 64, 0);
    k_tconv<<<(B_ * N_) / 4, 256, TCONV_SMEM>>>(d_xt1, d_xt0, W_t + 2 * 20480, b_t + 2 * 64, 0);

    k_mlp1<<<N_, 256, MLP1_SMEM>>>(d_xt0, W1);
    k_red<<<(G_ * 256) / 256, 256>>>(b1);
    k_mlp2<<<G_, 64>>>(W2, b2, out);
}

// round 3
// speedup vs baseline: 15.4480x; 14.3157x over previous
#include <cuda_runtime.h>
#include <cuda_bf16.h>
#include <math.h>

#define B_   4
#define T_   32
#define N_   370
#define E_   11840
#define E2_  (E_ + N_)       // 12210
#define G_   128             // B*T
#define H_   64
#define GN   (G_ * N_)       // 47360 = 740 * 64
#define NH   (N_ * H_)       // 23680
#define CHUNK_ 512
#define GAT_CAP 192

// ---------------- staged inputs (device copies) ----------------
__device__ float d_xin[GN * H_];
__device__ int   d_eic[2 * E_];
__device__ float d_ewc[E_];
__device__ float d_Wg[3 * 4096];
__device__ float d_bg[3 * 64];
__device__ float d_Wa[3 * 4096];
__device__ float d_asw[3 * 64];
__device__ float d_adw[3 * 64];
__device__ float d_ba[3 * 64];
__device__ float d_Wt[3 * 20480];
__device__ float d_bt[3 * 64];
__device__ float d_lngc[3 * 64];
__device__ float d_lnbc[3 * 64];
__device__ float d_W1c[NH * 256];
__device__ float d_b1c[256];
__device__ float d_W2c[256 * 64];
__device__ float d_b2c[64];

// ---------------- scratch ----------------
__device__ float  d_h[GN * H_];
__device__ float  d_bufA[GN * H_];
__device__ float  d_bufB[GN * H_];
__device__ float  d_asrc[GN * 4];
__device__ float  d_adst[GN * 4];
__device__ int    d_csr_ptr[N_ + 1];
__device__ int    d_csr_eid[E2_];
__device__ int    d_csr_dst[E2_];
__device__ float  d_dis[N_];
__device__ float2 d_csr_sg[E2_];      // {src (bits), gnorm} in CSR order
__device__ int    d_cnt[CHUNK_ * N_];
__device__ float  d_xt0[B_ * N_ * H_ * T_];
__device__ float  d_xt1[B_ * N_ * H_ * T_];
__device__ float  d_part[N_ * G_ * 256];

__device__ __forceinline__ float gelu_f(float x) {
    return 0.5f * x * (1.0f + erff(x * 0.70710678118654752f));
}

// ---------------- prepA: deterministic CSR (1 block) ----------------
__global__ void k_prepA() {
    int t = threadIdx.x;                 // 512 threads
    const int* srcs = d_eic;
    const int* dsts = d_eic + E_;
    const int EC = (E_ + CHUNK_ - 1) / CHUNK_;       // 24
    int e0 = t * EC;
    int e1 = min(e0 + EC, E_);
    __shared__ int ptr_s[N_ + 1];
    (void)srcs;

    for (int i = t; i < CHUNK_ * N_; i += CHUNK_) d_cnt[i] = 0;
    __syncthreads();
    for (int e = e0; e < e1; e++) d_cnt[t * N_ + dsts[e]]++;
    __syncthreads();
    if (t < N_) {
        int run = 0;
        for (int c = 0; c < CHUNK_; c++) {
            int idx = c * N_ + t;
            int v = d_cnt[idx];
            d_cnt[idx] = run;
            run += v;
        }
        ptr_s[t] = run + 1;              // + self loop
    }
    __syncthreads();
    if (t == 0) {
        int p = 0;
        for (int n = 0; n < N_; n++) { int v = ptr_s[n]; ptr_s[n] = p; p += v; }
        ptr_s[N_] = p;                   // == E2_
    }
    __syncthreads();
    if (t <= N_) d_csr_ptr[t] = ptr_s[t];
    // stable fill (chunk order == edge order)
    for (int e = e0; e < e1; e++) {
        int d = dsts[e];
        int pos = ptr_s[d] + d_cnt[t * N_ + d]++;
        d_csr_eid[pos] = e;
        d_csr_dst[pos] = d;
    }
    __syncthreads();
    if (t < N_) {
        int pos = ptr_s[t + 1] - 1;      // self-loop last
        d_csr_eid[pos] = E_ + t;
        d_csr_dst[pos] = t;
    }
}

// ---------------- prepB: degree -> dis, warp per node ----------------
__global__ void k_prepB() {
    int n = blockIdx.x * 4 + (threadIdx.x >> 5);
    int lane = threadIdx.x & 31;
    if (n >= N_) return;
    int p0 = d_csr_ptr[n], p1 = d_csr_ptr[n + 1] - 1;   // exclude self
    float s = 0.0f;
    for (int p = p0 + lane; p < p1; p += 32) s += d_ewc[d_csr_eid[p]];
    #pragma unroll
    for (int off = 16; off > 0; off >>= 1) s += __shfl_xor_sync(0xffffffffu, s, off);
    if (lane == 0) d_dis[n] = rsqrtf(s + 1.0f);
}

// ---------------- prepC: packed (src,gnorm) ----------------
__global__ void k_prepC() {
    int pos = blockIdx.x * 256 + threadIdx.x;
    if (pos >= E2_) return;
    int e = d_csr_eid[pos], d = d_csr_dst[pos];
    float dd = d_dis[d];
    int s; float gn;
    if (e < E_) { s = d_eic[e]; gn = d_dis[s] * d_ewc[e] * dd; }
    else        { s = d;        gn = dd * dd; }
    d_csr_sg[pos] = make_float2(__int_as_float(s), gn);
}

// ------- 64x64 GEMM, 4x4 register tile; optional fused attention scores -------
__global__ void k_gemm64(const float* __restrict__ in, const float* __restrict__ W,
                         float* __restrict__ out, const float* __restrict__ awsrc,
                         const float* __restrict__ awdst, int do_att) {
    __shared__ __align__(16) float XsT[64 * 68];   // [k][r]
    __shared__ __align__(16) float Ws[64 * 64];    // [k][c]
    int tid = threadIdx.x;
    int r0 = blockIdx.x * 64;
    for (int i = tid; i < 4096; i += 256) Ws[i] = W[i];
    for (int i = tid; i < 4096; i += 256) {
        int r = i >> 6, k = i & 63;
        XsT[k * 68 + r] = in[(size_t)(r0 + r) * 64 + k];
    }
    __syncthreads();
    int tx = tid & 15, ty = tid >> 4;
    int c0 = tx * 4, rr = ty * 4;
    float acc[4][4] = {};
    #pragma unroll 4
    for (int k = 0; k < 64; k++) {
        float4 a4 = *(const float4*)&XsT[k * 68 + rr];
        float4 b4 = *(const float4*)&Ws[k * 64 + c0];
        float a[4] = {a4.x, a4.y, a4.z, a4.w};
        float b[4] = {b4.x, b4.y, b4.z, b4.w};
        #pragma unroll
        for (int i = 0; i < 4; i++)
            #pragma unroll
            for (int j = 0; j < 4; j++)
                acc[i][j] = fmaf(a[i], b[j], acc[i][j]);
    }
    #pragma unroll
    for (int i = 0; i < 4; i++) {
        float4 v = make_float4(acc[i][0], acc[i][1], acc[i][2], acc[i][3]);
        *(float4*)&out[(size_t)(r0 + rr + i) * 64 + c0] = v;
    }
    if (do_att) {
        float4 ws4 = *(const float4*)&awsrc[c0];
        float4 wd4 = *(const float4*)&awdst[c0];
        int hd = tx >> 2;
        #pragma unroll
        for (int i = 0; i < 4; i++) {
            float sa = acc[i][0] * ws4.x + acc[i][1] * ws4.y
                     + acc[i][2] * ws4.z + acc[i][3] * ws4.w;
            float da = acc[i][0] * wd4.x + acc[i][1] * wd4.y
                     + acc[i][2] * wd4.z + acc[i][3] * wd4.w;
            sa += __shfl_xor_sync(0xffffffffu, sa, 1);
            sa += __shfl_xor_sync(0xffffffffu, sa, 2);
            da += __shfl_xor_sync(0xffffffffu, da, 1);
            da += __shfl_xor_sync(0xffffffffu, da, 2);
            if ((tx & 3) == 0) {
                int r = r0 + rr + i;
                d_asrc[(size_t)r * 4 + hd] = sa;
                d_adst[(size_t)r * 4 + hd] = da;
            }
        }
    }
}

// ---------------- GCN aggregate + bias + GELU ----------------
__global__ void k_gcn_agg(const float* __restrict__ hw, const float* __restrict__ bias,
                          float* __restrict__ out) {
    int bid = blockIdx.x;
    int g = bid / N_, dstn = bid % N_;
    int c = threadIdx.x;
    int p0 = d_csr_ptr[dstn], p1 = d_csr_ptr[dstn + 1];
    const float* base = hw + (size_t)g * NH;
    float a0 = 0.f, a1 = 0.f, a2 = 0.f, a3 = 0.f;
    int p = p0;
    for (; p + 4 <= p1; p += 4) {
        float2 e0 = d_csr_sg[p];
        float2 e1 = d_csr_sg[p + 1];
        float2 e2 = d_csr_sg[p + 2];
        float2 e3 = d_csr_sg[p + 3];
        a0 = fmaf(e0.y, base[__float_as_int(e0.x) * 64 + c], a0);
        a1 = fmaf(e1.y, base[__float_as_int(e1.x) * 64 + c], a1);
        a2 = fmaf(e2.y, base[__float_as_int(e2.x) * 64 + c], a2);
        a3 = fmaf(e3.y, base[__float_as_int(e3.x) * 64 + c], a3);
    }
    for (; p < p1; p++) {
        float2 e = d_csr_sg[p];
        a0 = fmaf(e.y, base[__float_as_int(e.x) * 64 + c], a0);
    }
    float acc = (a0 + a1) + (a2 + a3) + bias[c];
    out[(size_t)bid * 64 + c] = gelu_f(acc);
}

// ------- GAT: edge softmax (single expf) + gather + bias + residual + LN -------
__global__ void k_gat(const float* __restrict__ gh, const float* __restrict__ bias,
                      const float* __restrict__ lng, const float* __restrict__ lnb,
                      const float* __restrict__ hin, float* __restrict__ hout) {
    __shared__ int   s_src[GAT_CAP];
    __shared__ float s_a[GAT_CAP * 4];
    __shared__ float s_red[8];
    __shared__ float s_m[4], s_d[4];
    __shared__ float lnred[4];
    int bid = blockIdx.x;
    int g = bid / N_, dstn = bid % N_;
    int tid = threadIdx.x;
    int p0 = d_csr_ptr[dstn], p1 = d_csr_ptr[dstn + 1];
    int deg = p1 - p0;
    const float* asr = d_asrc + (size_t)g * (N_ * 4);
    float4 ad = *(const float4*)&d_adst[(size_t)bid * 4];
    int c = tid, hh = c >> 4;
    const float* ghb = gh + (size_t)g * NH;
    float accv;

    if (deg <= GAT_CAP) {
        float m0 = -1e30f, m1 = -1e30f, m2 = -1e30f, m3 = -1e30f;
        for (int j = tid; j < deg; j += 64) {
            float2 sg = d_csr_sg[p0 + j];
            int s = __float_as_int(sg.x);
            float4 av = *(const float4*)&asr[s * 4];
            float a0 = av.x + ad.x, a1 = av.y + ad.y, a2 = av.z + ad.z, a3 = av.w + ad.w;
            a0 = fmaxf(a0, 0.2f * a0); a1 = fmaxf(a1, 0.2f * a1);
            a2 = fmaxf(a2, 0.2f * a2); a3 = fmaxf(a3, 0.2f * a3);
            s_src[j] = s;
            s_a[j * 4 + 0] = a0; s_a[j * 4 + 1] = a1;
            s_a[j * 4 + 2] = a2; s_a[j * 4 + 3] = a3;
            m0 = fmaxf(m0, a0); m1 = fmaxf(m1, a1);
            m2 = fmaxf(m2, a2); m3 = fmaxf(m3, a3);
        }
        #pragma unroll
        for (int off = 16; off > 0; off >>= 1) {
            m0 = fmaxf(m0, __shfl_xor_sync(0xffffffffu, m0, off));
            m1 = fmaxf(m1, __shfl_xor_sync(0xffffffffu, m1, off));
            m2 = fmaxf(m2, __shfl_xor_sync(0xffffffffu, m2, off));
            m3 = fmaxf(m3, __shfl_xor_sync(0xffffffffu, m3, off));
        }
        if ((tid & 31) == 0) {
            int w = tid >> 5;
            s_red[w * 4 + 0] = m0; s_red[w * 4 + 1] = m1;
            s_red[w * 4 + 2] = m2; s_red[w * 4 + 3] = m3;
        }
        __syncthreads();
        if (tid < 4) s_m[tid] = fmaxf(s_red[tid], s_red[4 + tid]);
        __syncthreads();
        float M0 = s_m[0], M1 = s_m[1], M2 = s_m[2], M3 = s_m[3];
        float d0 = 0.f, d1 = 0.f, d2 = 0.f, d3 = 0.f;
        for (int j = tid; j < deg; j += 64) {
            float e0 = expf(s_a[j * 4 + 0] - M0);
            float e1 = expf(s_a[j * 4 + 1] - M1);
            float e2 = expf(s_a[j * 4 + 2] - M2);
            float e3 = expf(s_a[j * 4 + 3] - M3);
            s_a[j * 4 + 0] = e0; s_a[j * 4 + 1] = e1;
            s_a[j * 4 + 2] = e2; s_a[j * 4 + 3] = e3;
            d0 += e0; d1 += e1; d2 += e2; d3 += e3;
        }
        #pragma unroll
        for (int off = 16; off > 0; off >>= 1) {
            d0 += __shfl_xor_sync(0xffffffffu, d0, off);
            d1 += __shfl_xor_sync(0xffffffffu, d1, off);
            d2 += __shfl_xor_sync(0xffffffffu, d2, off);
            d3 += __shfl_xor_sync(0xffffffffu, d3, off);
        }
        if ((tid & 31) == 0) {
            int w = tid >> 5;
            s_red[w * 4 + 0] = d0; s_red[w * 4 + 1] = d1;
            s_red[w * 4 + 2] = d2; s_red[w * 4 + 3] = d3;
        }
        __syncthreads();
        if (tid < 4) s_d[tid] = 1.0f / (s_red[tid] + s_red[4 + tid]);
        __syncthreads();
        float inv = s_d[hh];
        float a0 = 0.f, a1 = 0.f, a2 = 0.f, a3 = 0.f;
        int j = 0;
        for (; j + 4 <= deg; j += 4) {
            a0 = fmaf(s_a[(j + 0) * 4 + hh], ghb[s_src[j + 0] * 64 + c], a0);
            a1 = fmaf(s_a[(j + 1) * 4 + hh], ghb[s_src[j + 1] * 64 + c], a1);
            a2 = fmaf(s_a[(j + 2) * 4 + hh], ghb[s_src[j + 2] * 64 + c], a2);
            a3 = fmaf(s_a[(j + 3) * 4 + hh], ghb[s_src[j + 3] * 64 + c], a3);
        }
        for (; j < deg; j++)
            a0 = fmaf(s_a[j * 4 + hh], ghb[s_src[j] * 64 + c], a0);
        accv = ((a0 + a1) + (a2 + a3)) * inv;
    } else {
        float adh = (hh == 0) ? ad.x : (hh == 1) ? ad.y : (hh == 2) ? ad.z : ad.w;
        float m = -1e30f;
        for (int p = p0; p < p1; p++) {
            float2 sg = d_csr_sg[p];
            float a = asr[__float_as_int(sg.x) * 4 + hh] + adh;
            a = fmaxf(a, 0.2f * a);
            m = fmaxf(m, a);
        }
        float den = 0.f;
        for (int p = p0; p < p1; p++) {
            float2 sg = d_csr_sg[p];
            float a = asr[__float_as_int(sg.x) * 4 + hh] + adh;
            a = fmaxf(a, 0.2f * a);
            den += expf(a - m);
        }
        float inv = 1.0f / den;
        float acc = 0.f;
        for (int p = p0; p < p1; p++) {
            float2 sg = d_csr_sg[p];
            int s = __float_as_int(sg.x);
            float a = asr[s * 4 + hh] + adh;
            a = fmaxf(a, 0.2f * a);
            acc = fmaf(expf(a - m) * inv, ghb[s * 64 + c], acc);
        }
        accv = acc;
    }

    float r = accv + bias[c] + hin[(size_t)bid * 64 + c];
    float s1 = r, s2 = r * r;
    #pragma unroll
    for (int off = 16; off > 0; off >>= 1) {
        s1 += __shfl_xor_sync(0xffffffffu, s1, off);
        s2 += __shfl_xor_sync(0xffffffffu, s2, off);
    }
    __syncthreads();
    if ((c & 31) == 0) { lnred[(c >> 5) * 2] = s1; lnred[(c >> 5) * 2 + 1] = s2; }
    __syncthreads();
    float tot = lnred[0] + lnred[2];
    float tot2 = lnred[1] + lnred[3];
    float mu = tot * (1.0f / 64.0f);
    float var = fmaxf(tot2 * (1.0f / 64.0f) - mu * mu, 0.0f);
    hout[(size_t)bid * 64 + c] = (r - mu) * rsqrtf(var + 1e-5f) * lng[c] + lnb[c];
}

// ---------------- temporal conv: out = gelu(conv(in)+b) + in, 4 bn per block ----------------
#define WS_FLOATS (320 * 65)                 // 20800
#define XS_STRIDE 40
#define XS_PER_BN (64 * XS_STRIDE)           // 2560
#define TCONV_SMEM ((WS_FLOATS + 4 * XS_PER_BN) * 4)

#define PUT4(q, idx) do { xw[idx] = q.x; xw[idx + 1] = q.y; \
                          xw[idx + 2] = q.z; xw[idx + 3] = q.w; } while (0)

__global__ void k_tconv(const float* __restrict__ in, float* __restrict__ out,
                        const float* __restrict__ W, const float* __restrict__ bias,
                        int from_h) {
    extern __shared__ __align__(16) float sm[];
    float* ws = sm;                          // [r=i*5+k][o], stride 65
    float* xs = sm + WS_FLOATS;              // 4 bn x 64 i x 40 (halo at ends)
    int tid = threadIdx.x;
    int bn0 = blockIdx.x * 4;

    for (int i = tid; i < 20480; i += 256) {
        int o = i / 320, r = i % 320;
        ws[r * 65 + o] = W[i];
    }
    for (int i = tid; i < 4 * XS_PER_BN; i += 256) xs[i] = 0.0f;
    __syncthreads();
    for (int idx = tid; idx < 4 * 2048; idx += 256) {
        int bnL = idx >> 11;
        int r = idx & 2047;
        int bn = bn0 + bnL;
        float v;
        int i2, tt;
        if (from_h) {
            tt = r >> 6; i2 = r & 63;
            int b = bn / N_, n = bn % N_;
            v = in[(((size_t)(b * 32 + tt) * N_) + n) * 64 + i2];
        } else {
            i2 = r >> 5; tt = r & 31;
            v = in[(size_t)bn * 2048 + r];
        }
        xs[bnL * XS_PER_BN + i2 * XS_STRIDE + 4 + tt] = v;
    }
    __syncthreads();

    int o = tid & 63, bnL = tid >> 6;
    const float* xr = xs + bnL * XS_PER_BN;
    float acc[32];
    float bo = bias[o];
    #pragma unroll
    for (int t = 0; t < 32; t++) acc[t] = bo;
    for (int i = 0; i < 64; i++) {
        const float* xi = xr + i * XS_STRIDE;
        float4 q0 = *(const float4*)(xi +  0);
        float4 q1 = *(const float4*)(xi +  4);
        float4 q2 = *(const float4*)(xi +  8);
        float4 q3 = *(const float4*)(xi + 12);
        float4 q4 = *(const float4*)(xi + 16);
        float4 q5 = *(const float4*)(xi + 20);
        float4 q6 = *(const float4*)(xi + 24);
        float4 q7 = *(const float4*)(xi + 28);
        float4 q8 = *(const float4*)(xi + 32);
        float4 q9 = *(const float4*)(xi + 36);
        float xw[40];
        PUT4(q0, 0);  PUT4(q1, 4);  PUT4(q2, 8);  PUT4(q3, 12); PUT4(q4, 16);
        PUT4(q5, 20); PUT4(q6, 24); PUT4(q7, 28); PUT4(q8, 32); PUT4(q9, 36);
        float w0 = ws[(i * 5 + 0) * 65 + o];
        float w1 = ws[(i * 5 + 1) * 65 + o];
        float w2 = ws[(i * 5 + 2) * 65 + o];
        float w3 = ws[(i * 5 + 3) * 65 + o];
        float w4 = ws[(i * 5 + 4) * 65 + o];
        #pragma unroll
        for (int t = 0; t < 32; t++) {
            float a = acc[t];
            a = fmaf(xw[t + 2], w0, a);
            a = fmaf(xw[t + 3], w1, a);
            a = fmaf(xw[t + 4], w2, a);
            a = fmaf(xw[t + 5], w3, a);
            a = fmaf(xw[t + 6], w4, a);
            acc[t] = a;
        }
    }
    int bn = bn0 + bnL;
    float* ob = out + (size_t)bn * 2048 + o * 32;
    #pragma unroll
    for (int t = 0; t < 32; t++) {
        float xin = xr[o * XS_STRIDE + 4 + t];
        ob[t] = gelu_f(acc[t]) + xin;
    }
}

// ---------------- MLP1 split-K over nodes: 4g x 8o register tiles ----------------
#define ZS_STRIDE 65
#define MLP1_SMEM ((G_ * ZS_STRIDE + 64 * 256) * 4)
__global__ void k_mlp1(const float* __restrict__ xt, const float* __restrict__ W1) {
    extern __shared__ __align__(16) float sm[];
    float* zs  = sm;                       // [g][k], stride 65
    float* w1s = sm + G_ * ZS_STRIDE;      // [k][o]
    int n = blockIdx.x, tid = threadIdx.x;
    for (int i = tid; i < 8192; i += 256) {
        int b = i >> 11, c = (i >> 5) & 63, t = i & 31;
        zs[(b * 32 + t) * ZS_STRIDE + c] = xt[(((size_t)(b * N_ + n)) * 64 + c) * 32 + t];
    }
    for (int i = tid; i < 16384; i += 256)
        w1s[i] = W1[(size_t)n * 16384 + i];
    __syncthreads();
    int ow = tid & 31, gw = tid >> 5;
    int o0 = ow * 8;
    float* pb = d_part + (size_t)n * (G_ * 256);
    for (int pass = 0; pass < 4; pass++) {
        int g0 = pass * 32 + gw * 4;
        float acc[4][8] = {};
        #pragma unroll 4
        for (int k = 0; k < 64; k++) {
            float4 wa = *(const float4*)&w1s[k * 256 + o0];
            float4 wb = *(const float4*)&w1s[k * 256 + o0 + 4];
            float w[8] = {wa.x, wa.y, wa.z, wa.w, wb.x, wb.y, wb.z, wb.w};
            float z[4];
            #pragma unroll
            for (int j = 0; j < 4; j++) z[j] = zs[(g0 + j) * ZS_STRIDE + k];
            #pragma unroll
            for (int j = 0; j < 4; j++)
                #pragma unroll
                for (int q = 0; q < 8; q++)
                    acc[j][q] = fmaf(z[j], w[q], acc[j][q]);
        }
        #pragma unroll
        for (int j = 0; j < 4; j++) {
            *(float4*)&pb[(g0 + j) * 256 + o0]     = make_float4(acc[j][0], acc[j][1], acc[j][2], acc[j][3]);
            *(float4*)&pb[(g0 + j) * 256 + o0 + 4] = make_float4(acc[j][4], acc[j][5], acc[j][6], acc[j][7]);
        }
    }
}

// ---------------- reduce partials + bias + GELU + MLP2, fused ----------------
__global__ void k_redmlp2(const float* __restrict__ b1, const float* __restrict__ W2,
                          const float* __restrict__ b2, float* __restrict__ out) {
    __shared__ float hid[256];
    int g = blockIdx.x, o = threadIdx.x;
    float a0 = 0.f, a1 = 0.f;
    size_t base = (size_t)g * 256 + o;
    int nb = 0;
    for (; nb + 2 <= N_; nb += 2) {
        a0 += d_part[(size_t)nb * (G_ * 256) + base];
        a1 += d_part[(size_t)(nb + 1) * (G_ * 256) + base];
    }
    for (; nb < N_; nb++) a0 += d_part[(size_t)nb * (G_ * 256) + base];
    hid[o] = gelu_f(a0 + a1 + b1[o]);
    __syncthreads();
    if (o < 64) {
        float acc = b2[o];
        #pragma unroll 8
        for (int k = 0; k < 256; k++) acc = fmaf(hid[k], W2[k * 64 + o], acc);
        out[(size_t)g * 64 + o] = acc;
    }
}

// ---------------- host orchestration ----------------
extern "C" void kernel_launch(void* const* d_in, const int* in_sizes, int n_in,
                              void* d_out, int out_size) {
    float* out = (float*)d_out;

    cudaFuncSetAttribute(k_tconv, cudaFuncAttributeMaxDynamicSharedMemorySize, TCONV_SMEM);
    cudaFuncSetAttribute(k_mlp1,  cudaFuncAttributeMaxDynamicSharedMemorySize, MLP1_SMEM);

    // ---- stage all inputs into device globals (D2D async, graph-capturable) ----
    cudaMemcpyToSymbolAsync(d_xin,  d_in[0],  (size_t)GN * H_ * 4, 0, cudaMemcpyDeviceToDevice, 0);
    cudaMemcpyToSymbolAsync(d_eic,  d_in[1],  (size_t)2 * E_ * 4,  0, cudaMemcpyDeviceToDevice, 0);
    cudaMemcpyToSymbolAsync(d_ewc,  d_in[2],  (size_t)E_ * 4,      0, cudaMemcpyDeviceToDevice, 0);
    cudaMemcpyToSymbolAsync(d_Wg,   d_in[3],  (size_t)3 * 4096 * 4, 0, cudaMemcpyDeviceToDevice, 0);
    cudaMemcpyToSymbolAsync(d_bg,   d_in[4],  (size_t)3 * 64 * 4,   0, cudaMemcpyDeviceToDevice, 0);
    cudaMemcpyToSymbolAsync(d_Wa,   d_in[5],  (size_t)3 * 4096 * 4, 0, cudaMemcpyDeviceToDevice, 0);
    cudaMemcpyToSymbolAsync(d_asw,  d_in[6],  (size_t)3 * 64 * 4,   0, cudaMemcpyDeviceToDevice, 0);
    cudaMemcpyToSymbolAsync(d_adw,  d_in[7],  (size_t)3 * 64 * 4,   0, cudaMemcpyDeviceToDevice, 0);
    cudaMemcpyToSymbolAsync(d_ba,   d_in[8],  (size_t)3 * 64 * 4,   0, cudaMemcpyDeviceToDevice, 0);
    cudaMemcpyToSymbolAsync(d_Wt,   d_in[9],  (size_t)3 * 20480 * 4, 0, cudaMemcpyDeviceToDevice, 0);
    cudaMemcpyToSymbolAsync(d_bt,   d_in[10], (size_t)3 * 64 * 4,   0, cudaMemcpyDeviceToDevice, 0);
    cudaMemcpyToSymbolAsync(d_lngc, d_in[11], (size_t)3 * 64 * 4,   0, cudaMemcpyDeviceToDevice, 0);
    cudaMemcpyToSymbolAsync(d_lnbc, d_in[12], (size_t)3 * 64 * 4,   0, cudaMemcpyDeviceToDevice, 0);
    cudaMemcpyToSymbolAsync(d_W1c,  d_in[13], (size_t)NH * 256 * 4, 0, cudaMemcpyDeviceToDevice, 0);
    cudaMemcpyToSymbolAsync(d_b1c,  d_in[14], (size_t)256 * 4,      0, cudaMemcpyDeviceToDevice, 0);
    cudaMemcpyToSymbolAsync(d_W2c,  d_in[15], (size_t)256 * 64 * 4, 0, cudaMemcpyDeviceToDevice, 0);
    cudaMemcpyToSymbolAsync(d_b2c,  d_in[16], (size_t)64 * 4,       0, cudaMemcpyDeviceToDevice, 0);

    // device-global pointers (no host-side symbol lookup needed: use kernels' view)
    // We launch with pointers obtained from the device symbols via small helper casts.
    float* xin  = nullptr; cudaGetSymbolAddress((void**)&xin,  d_xin);
    float* Wg   = nullptr; cudaGetSymbolAddress((void**)&Wg,   d_Wg);
    float* bg   = nullptr; cudaGetSymbolAddress((void**)&bg,   d_bg);
    float* Wa   = nullptr; cudaGetSymbolAddress((void**)&Wa,   d_Wa);
    float* asw  = nullptr; cudaGetSymbolAddress((void**)&asw,  d_asw);
    float* adw  = nullptr; cudaGetSymbolAddress((void**)&adw,  d_adw);
    float* ba   = nullptr; cudaGetSymbolAddress((void**)&ba,   d_ba);
    float* Wt   = nullptr; cudaGetSymbolAddress((void**)&Wt,   d_Wt);
    float* bt   = nullptr; cudaGetSymbolAddress((void**)&bt,   d_bt);
    float* lng  = nullptr; cudaGetSymbolAddress((void**)&lng,  d_lngc);
    float* lnb  = nullptr; cudaGetSymbolAddress((void**)&lnb,  d_lnbc);
    float* W1   = nullptr; cudaGetSymbolAddress((void**)&W1,   d_W1c);
    float* b1   = nullptr; cudaGetSymbolAddress((void**)&b1,   d_b1c);
    float* W2   = nullptr; cudaGetSymbolAddress((void**)&W2,   d_W2c);
    float* b2   = nullptr; cudaGetSymbolAddress((void**)&b2,   d_b2c);
    float* hbuf = nullptr; cudaGetSymbolAddress((void**)&hbuf, d_h);
    float* bufA = nullptr; cudaGetSymbolAddress((void**)&bufA, d_bufA);
    float* bufB = nullptr; cudaGetSymbolAddress((void**)&bufB, d_bufB);
    float* xt0  = nullptr; cudaGetSymbolAddress((void**)&xt0,  d_xt0);
    float* xt1  = nullptr; cudaGetSymbolAddress((void**)&xt1,  d_xt1);

    k_prepA<<<1, CHUNK_>>>();
    k_prepB<<<(N_ + 3) / 4, 128>>>();
    k_prepC<<<(E2_ + 255) / 256, 256>>>();

    const float* hin = xin;
    for (int l = 0; l < 3; l++) {
        k_gemm64<<<GN / 64, 256>>>(hin, Wg + l * 4096, bufA, nullptr, nullptr, 0);
        k_gcn_agg<<<GN, 64>>>(bufA, bg + l * 64, bufB);
        k_gemm64<<<GN / 64, 256>>>(bufB, Wa + l * 4096, bufA, asw + l * 64, adw + l * 64, 1);
        k_gat<<<GN, 64>>>(bufA, ba + l * 64, lng + l * 64, lnb + l * 64, hin, hbuf);
        hin = hbuf;
    }

    k_tconv<<<(B_ * N_) / 4, 256, TCONV_SMEM>>>(hbuf, xt0, Wt + 0 * 20480, bt + 0 * 64, 1);
    k_tconv<<<(B_ * N_) / 4, 256, TCONV_SMEM>>>(xt0,  xt1, Wt + 1 * 20480, bt + 1 * 64, 0);
    k_tconv<<<(B_ * N_) / 4, 256, TCONV_SMEM>>>(xt1,  xt0, Wt + 2 * 20480, bt + 2 * 64, 0);

    k_mlp1<<<N_, 256, MLP1_SMEM>>>(xt0, W1);
    k_redmlp2<<<G_, 256>>>(b1, W2, b2, out);
}

// round 4
// speedup vs baseline: 15.5463x; 1.0064x over previous
#include <cuda_runtime.h>
#include <cuda_bf16.h>
#include <math.h>

#define B_   4
#define T_   32
#define N_   370
#define E_   11840
#define E2_  (E_ + N_)       // 12210
#define G_   128             // B*T
#define H_   64
#define GN   (G_ * N_)       // 47360 = 740 * 64
#define NH   (N_ * H_)       // 23680
#define CHUNK_ 512
#define GAT_CAP 192

// ---------------- staged inputs (device copies) ----------------
__device__ float d_xin[GN * H_];
__device__ int   d_eic[2 * E_];
__device__ float d_ewc[E_];
__device__ float d_Wg[3 * 4096];
__device__ float d_bg[3 * 64];
__device__ float d_Wa[3 * 4096];
__device__ float d_asw[3 * 64];
__device__ float d_adw[3 * 64];
__device__ float d_ba[3 * 64];
__device__ float d_Wt[3 * 20480];
__device__ float d_bt[3 * 64];
__device__ float d_lngc[3 * 64];
__device__ float d_lnbc[3 * 64];
__device__ float d_W1c[NH * 256];
__device__ float d_b1c[256];
__device__ float d_W2c[256 * 64];
__device__ float d_b2c[64];

// ---------------- scratch ----------------
__device__ float  d_h[GN * H_];
__device__ float  d_bufA[GN * H_];
__device__ float  d_bufB[GN * H_];
__device__ float  d_asrc[GN * 4];
__device__ float  d_adst[GN * 4];
__device__ int    d_csr_ptr[N_ + 1];
__device__ int    d_csr_eid[E2_];
__device__ int    d_csr_dst[E2_];
__device__ float  d_dis[N_];
__device__ float2 d_csr_sg[E2_];      // {src (bits), gnorm} in CSR order
__device__ int    d_cnt[CHUNK_ * N_];
__device__ float  d_xt0[B_ * N_ * H_ * T_];
__device__ float  d_xt1[B_ * N_ * H_ * T_];
__device__ float  d_part[N_ * G_ * 256];

__device__ __forceinline__ float gelu_f(float x) {
    return 0.5f * x * (1.0f + erff(x * 0.70710678118654752f));
}

// ---------------- prepA: deterministic CSR (1 block) ----------------
__global__ void k_prepA() {
    int t = threadIdx.x;                 // 512 threads
    const int* srcs = d_eic;
    const int* dsts = d_eic + E_;
    const int EC = (E_ + CHUNK_ - 1) / CHUNK_;       // 24
    int e0 = t * EC;
    int e1 = min(e0 + EC, E_);
    __shared__ int ptr_s[N_ + 1];
    (void)srcs;

    for (int i = t; i < CHUNK_ * N_; i += CHUNK_) d_cnt[i] = 0;
    __syncthreads();
    for (int e = e0; e < e1; e++) d_cnt[t * N_ + dsts[e]]++;
    __syncthreads();
    if (t < N_) {
        int run = 0;
        for (int c = 0; c < CHUNK_; c++) {
            int idx = c * N_ + t;
            int v = d_cnt[idx];
            d_cnt[idx] = run;
            run += v;
        }
        ptr_s[t] = run + 1;              // + self loop
    }
    __syncthreads();
    if (t == 0) {
        int p = 0;
        for (int n = 0; n < N_; n++) { int v = ptr_s[n]; ptr_s[n] = p; p += v; }
        ptr_s[N_] = p;                   // == E2_
    }
    __syncthreads();
    if (t <= N_) d_csr_ptr[t] = ptr_s[t];
    // stable fill (chunk order == edge order)
    for (int e = e0; e < e1; e++) {
        int d = dsts[e];
        int pos = ptr_s[d] + d_cnt[t * N_ + d]++;
        d_csr_eid[pos] = e;
        d_csr_dst[pos] = d;
    }
    __syncthreads();
    if (t < N_) {
        int pos = ptr_s[t + 1] - 1;      // self-loop last
        d_csr_eid[pos] = E_ + t;
        d_csr_dst[pos] = t;
    }
}

// ---------------- prepB: degree -> dis, warp per node ----------------
__global__ void k_prepB() {
    int n = blockIdx.x * 4 + (threadIdx.x >> 5);
    int lane = threadIdx.x & 31;
    if (n >= N_) return;
    int p0 = d_csr_ptr[n], p1 = d_csr_ptr[n + 1] - 1;   // exclude self
    float s = 0.0f;
    for (int p = p0 + lane; p < p1; p += 32) s += d_ewc[d_csr_eid[p]];
    #pragma unroll
    for (int off = 16; off > 0; off >>= 1) s += __shfl_xor_sync(0xffffffffu, s, off);
    if (lane == 0) d_dis[n] = rsqrtf(s + 1.0f);
}

// ---------------- prepC: packed (src,gnorm) ----------------
__global__ void k_prepC() {
    int pos = blockIdx.x * 256 + threadIdx.x;
    if (pos >= E2_) return;
    int e = d_csr_eid[pos], d = d_csr_dst[pos];
    float dd = d_dis[d];
    int s; float gn;
    if (e < E_) { s = d_eic[e]; gn = d_dis[s] * d_ewc[e] * dd; }
    else        { s = d;        gn = dd * dd; }
    d_csr_sg[pos] = make_float2(__int_as_float(s), gn);
}

// ------- 64x64 GEMM, 4x4 register tile; optional fused attention scores -------
__global__ void k_gemm64(const float* __restrict__ in, const float* __restrict__ W,
                         float* __restrict__ out, const float* __restrict__ awsrc,
                         const float* __restrict__ awdst, int do_att) {
    __shared__ __align__(16) float XsT[64 * 68];   // [k][r]
    __shared__ __align__(16) float Ws[64 * 64];    // [k][c]
    int tid = threadIdx.x;
    int r0 = blockIdx.x * 64;
    for (int i = tid; i < 4096; i += 256) Ws[i] = W[i];
    for (int i = tid; i < 4096; i += 256) {
        int r = i >> 6, k = i & 63;
        XsT[k * 68 + r] = in[(size_t)(r0 + r) * 64 + k];
    }
    __syncthreads();
    int tx = tid & 15, ty = tid >> 4;
    int c0 = tx * 4, rr = ty * 4;
    float acc[4][4] = {};
    #pragma unroll 4
    for (int k = 0; k < 64; k++) {
        float4 a4 = *(const float4*)&XsT[k * 68 + rr];
        float4 b4 = *(const float4*)&Ws[k * 64 + c0];
        float a[4] = {a4.x, a4.y, a4.z, a4.w};
        float b[4] = {b4.x, b4.y, b4.z, b4.w};
        #pragma unroll
        for (int i = 0; i < 4; i++)
            #pragma unroll
            for (int j = 0; j < 4; j++)
                acc[i][j] = fmaf(a[i], b[j], acc[i][j]);
    }
    #pragma unroll
    for (int i = 0; i < 4; i++) {
        float4 v = make_float4(acc[i][0], acc[i][1], acc[i][2], acc[i][3]);
        *(float4*)&out[(size_t)(r0 + rr + i) * 64 + c0] = v;
    }
    if (do_att) {
        float4 ws4 = *(const float4*)&awsrc[c0];
        float4 wd4 = *(const float4*)&awdst[c0];
        int hd = tx >> 2;
        #pragma unroll
        for (int i = 0; i < 4; i++) {
            float sa = acc[i][0] * ws4.x + acc[i][1] * ws4.y
                     + acc[i][2] * ws4.z + acc[i][3] * ws4.w;
            float da = acc[i][0] * wd4.x + acc[i][1] * wd4.y
                     + acc[i][2] * wd4.z + acc[i][3] * wd4.w;
            sa += __shfl_xor_sync(0xffffffffu, sa, 1);
            sa += __shfl_xor_sync(0xffffffffu, sa, 2);
            da += __shfl_xor_sync(0xffffffffu, da, 1);
            da += __shfl_xor_sync(0xffffffffu, da, 2);
            if ((tx & 3) == 0) {
                int r = r0 + rr + i;
                d_asrc[(size_t)r * 4 + hd] = sa;
                d_adst[(size_t)r * 4 + hd] = da;
            }
        }
    }
}

// ---------------- GCN aggregate + bias + GELU ----------------
__global__ void k_gcn_agg(const float* __restrict__ hw, const float* __restrict__ bias,
                          float* __restrict__ out) {
    int bid = blockIdx.x;
    int g = bid / N_, dstn = bid % N_;
    int c = threadIdx.x;
    int p0 = d_csr_ptr[dstn], p1 = d_csr_ptr[dstn + 1];
    const float* base = hw + (size_t)g * NH;
    float a0 = 0.f, a1 = 0.f, a2 = 0.f, a3 = 0.f;
    int p = p0;
    for (; p + 4 <= p1; p += 4) {
        float2 e0 = d_csr_sg[p];
        float2 e1 = d_csr_sg[p + 1];
        float2 e2 = d_csr_sg[p + 2];
        float2 e3 = d_csr_sg[p + 3];
        a0 = fmaf(e0.y, base[__float_as_int(e0.x) * 64 + c], a0);
        a1 = fmaf(e1.y, base[__float_as_int(e1.x) * 64 + c], a1);
        a2 = fmaf(e2.y, base[__float_as_int(e2.x) * 64 + c], a2);
        a3 = fmaf(e3.y, base[__float_as_int(e3.x) * 64 + c], a3);
    }
    for (; p < p1; p++) {
        float2 e = d_csr_sg[p];
        a0 = fmaf(e.y, base[__float_as_int(e.x) * 64 + c], a0);
    }
    float acc = (a0 + a1) + (a2 + a3) + bias[c];
    out[(size_t)bid * 64 + c] = gelu_f(acc);
}

// ------- GAT: edge softmax (single expf) + gather + bias + residual + LN -------
__global__ void k_gat(const float* __restrict__ gh, const float* __restrict__ bias,
                      const float* __restrict__ lng, const float* __restrict__ lnb,
                      const float* __restrict__ hin, float* __restrict__ hout) {
    __shared__ int   s_src[GAT_CAP];
    __shared__ float s_a[GAT_CAP * 4];
    __shared__ float s_red[8];
    __shared__ float s_m[4], s_d[4];
    __shared__ float lnred[4];
    int bid = blockIdx.x;
    int g = bid / N_, dstn = bid % N_;
    int tid = threadIdx.x;
    int p0 = d_csr_ptr[dstn], p1 = d_csr_ptr[dstn + 1];
    int deg = p1 - p0;
    const float* asr = d_asrc + (size_t)g * (N_ * 4);
    float4 ad = *(const float4*)&d_adst[(size_t)bid * 4];
    int c = tid, hh = c >> 4;
    const float* ghb = gh + (size_t)g * NH;
    float accv;

    if (deg <= GAT_CAP) {
        float m0 = -1e30f, m1 = -1e30f, m2 = -1e30f, m3 = -1e30f;
        for (int j = tid; j < deg; j += 64) {
            float2 sg = d_csr_sg[p0 + j];
            int s = __float_as_int(sg.x);
            float4 av = *(const float4*)&asr[s * 4];
            float a0 = av.x + ad.x, a1 = av.y + ad.y, a2 = av.z + ad.z, a3 = av.w + ad.w;
            a0 = fmaxf(a0, 0.2f * a0); a1 = fmaxf(a1, 0.2f * a1);
            a2 = fmaxf(a2, 0.2f * a2); a3 = fmaxf(a3, 0.2f * a3);
            s_src[j] = s;
            s_a[j * 4 + 0] = a0; s_a[j * 4 + 1] = a1;
            s_a[j * 4 + 2] = a2; s_a[j * 4 + 3] = a3;
            m0 = fmaxf(m0, a0); m1 = fmaxf(m1, a1);
            m2 = fmaxf(m2, a2); m3 = fmaxf(m3, a3);
        }
        #pragma unroll
        for (int off = 16; off > 0; off >>= 1) {
            m0 = fmaxf(m0, __shfl_xor_sync(0xffffffffu, m0, off));
            m1 = fmaxf(m1, __shfl_xor_sync(0xffffffffu, m1, off));
            m2 = fmaxf(m2, __shfl_xor_sync(0xffffffffu, m2, off));
            m3 = fmaxf(m3, __shfl_xor_sync(0xffffffffu, m3, off));
        }
        if ((tid & 31) == 0) {
            int w = tid >> 5;
            s_red[w * 4 + 0] = m0; s_red[w * 4 + 1] = m1;
            s_red[w * 4 + 2] = m2; s_red[w * 4 + 3] = m3;
        }
        __syncthreads();
        if (tid < 4) s_m[tid] = fmaxf(s_red[tid], s_red[4 + tid]);
        __syncthreads();
        float M0 = s_m[0], M1 = s_m[1], M2 = s_m[2], M3 = s_m[3];
        float d0 = 0.f, d1 = 0.f, d2 = 0.f, d3 = 0.f;
        for (int j = tid; j < deg; j += 64) {
            float e0 = expf(s_a[j * 4 + 0] - M0);
            float e1 = expf(s_a[j * 4 + 1] - M1);
            float e2 = expf(s_a[j * 4 + 2] - M2);
            float e3 = expf(s_a[j * 4 + 3] - M3);
            s_a[j * 4 + 0] = e0; s_a[j * 4 + 1] = e1;
            s_a[j * 4 + 2] = e2; s_a[j * 4 + 3] = e3;
            d0 += e0; d1 += e1; d2 += e2; d3 += e3;
        }
        #pragma unroll
        for (int off = 16; off > 0; off >>= 1) {
            d0 += __shfl_xor_sync(0xffffffffu, d0, off);
            d1 += __shfl_xor_sync(0xffffffffu, d1, off);
            d2 += __shfl_xor_sync(0xffffffffu, d2, off);
            d3 += __shfl_xor_sync(0xffffffffu, d3, off);
        }
        if ((tid & 31) == 0) {
            int w = tid >> 5;
            s_red[w * 4 + 0] = d0; s_red[w * 4 + 1] = d1;
            s_red[w * 4 + 2] = d2; s_red[w * 4 + 3] = d3;
        }
        __syncthreads();
        if (tid < 4) s_d[tid] = 1.0f / (s_red[tid] + s_red[4 + tid]);
        __syncthreads();
        float inv = s_d[hh];
        float a0 = 0.f, a1 = 0.f, a2 = 0.f, a3 = 0.f;
        int j = 0;
        for (; j + 4 <= deg; j += 4) {
            a0 = fmaf(s_a[(j + 0) * 4 + hh], ghb[s_src[j + 0] * 64 + c], a0);
            a1 = fmaf(s_a[(j + 1) * 4 + hh], ghb[s_src[j + 1] * 64 + c], a1);
            a2 = fmaf(s_a[(j + 2) * 4 + hh], ghb[s_src[j + 2] * 64 + c], a2);
            a3 = fmaf(s_a[(j + 3) * 4 + hh], ghb[s_src[j + 3] * 64 + c], a3);
        }
        for (; j < deg; j++)
            a0 = fmaf(s_a[j * 4 + hh], ghb[s_src[j] * 64 + c], a0);
        accv = ((a0 + a1) + (a2 + a3)) * inv;
    } else {
        float adh = (hh == 0) ? ad.x : (hh == 1) ? ad.y : (hh == 2) ? ad.z : ad.w;
        float m = -1e30f;
        for (int p = p0; p < p1; p++) {
            float2 sg = d_csr_sg[p];
            float a = asr[__float_as_int(sg.x) * 4 + hh] + adh;
            a = fmaxf(a, 0.2f * a);
            m = fmaxf(m, a);
        }
        float den = 0.f;
        for (int p = p0; p < p1; p++) {
            float2 sg = d_csr_sg[p];
            float a = asr[__float_as_int(sg.x) * 4 + hh] + adh;
            a = fmaxf(a, 0.2f * a);
            den += expf(a - m);
        }
        float inv = 1.0f / den;
        float acc = 0.f;
        for (int p = p0; p < p1; p++) {
            float2 sg = d_csr_sg[p];
            int s = __float_as_int(sg.x);
            float a = asr[s * 4 + hh] + adh;
            a = fmaxf(a, 0.2f * a);
            acc = fmaf(expf(a - m) * inv, ghb[s * 64 + c], acc);
        }
        accv = acc;
    }

    float r = accv + bias[c] + hin[(size_t)bid * 64 + c];
    float s1 = r, s2 = r * r;
    #pragma unroll
    for (int off = 16; off > 0; off >>= 1) {
        s1 += __shfl_xor_sync(0xffffffffu, s1, off);
        s2 += __shfl_xor_sync(0xffffffffu, s2, off);
    }
    __syncthreads();
    if ((c & 31) == 0) { lnred[(c >> 5) * 2] = s1; lnred[(c >> 5) * 2 + 1] = s2; }
    __syncthreads();
    float tot = lnred[0] + lnred[2];
    float tot2 = lnred[1] + lnred[3];
    float mu = tot * (1.0f / 64.0f);
    float var = fmaxf(tot2 * (1.0f / 64.0f) - mu * mu, 0.0f);
    hout[(size_t)bid * 64 + c] = (r - mu) * rsqrtf(var + 1e-5f) * lng[c] + lnb[c];
}

// ---------------- temporal conv: out = gelu(conv(in)+b) + in, 4 bn per block ----------------
#define WS_FLOATS (320 * 65)                 // 20800
#define XS_STRIDE 40
#define XS_PER_BN (64 * XS_STRIDE)           // 2560
#define TCONV_SMEM ((WS_FLOATS + 4 * XS_PER_BN) * 4)

#define PUT4(q, idx) do { xw[idx] = q.x; xw[idx + 1] = q.y; \
                          xw[idx + 2] = q.z; xw[idx + 3] = q.w; } while (0)

__global__ void k_tconv(const float* __restrict__ in, float* __restrict__ out,
                        const float* __restrict__ W, const float* __restrict__ bias,
                        int from_h) {
    extern __shared__ __align__(16) float sm[];
    float* ws = sm;                          // [r=i*5+k][o], stride 65
    float* xs = sm + WS_FLOATS;              // 4 bn x 64 i x 40 (halo at ends)
    int tid = threadIdx.x;
    int bn0 = blockIdx.x * 4;

    for (int i = tid; i < 20480; i += 256) {
        int o = i / 320, r = i % 320;
        ws[r * 65 + o] = W[i];
    }
    for (int i = tid; i < 4 * XS_PER_BN; i += 256) xs[i] = 0.0f;
    __syncthreads();
    for (int idx = tid; idx < 4 * 2048; idx += 256) {
        int bnL = idx >> 11;
        int r = idx & 2047;
        int bn = bn0 + bnL;
        float v;
        int i2, tt;
        if (from_h) {
            tt = r >> 6; i2 = r & 63;
            int b = bn / N_, n = bn % N_;
            v = in[(((size_t)(b * 32 + tt) * N_) + n) * 64 + i2];
        } else {
            i2 = r >> 5; tt = r & 31;
            v = in[(size_t)bn * 2048 + r];
        }
        xs[bnL * XS_PER_BN + i2 * XS_STRIDE + 4 + tt] = v;
    }
    __syncthreads();

    int o = tid & 63, bnL = tid >> 6;
    const float* xr = xs + bnL * XS_PER_BN;
    float acc[32];
    float bo = bias[o];
    #pragma unroll
    for (int t = 0; t < 32; t++) acc[t] = bo;
    for (int i = 0; i < 64; i++) {
        const float* xi = xr + i * XS_STRIDE;
        float4 q0 = *(const float4*)(xi +  0);
        float4 q1 = *(const float4*)(xi +  4);
        float4 q2 = *(const float4*)(xi +  8);
        float4 q3 = *(const float4*)(xi + 12);
        float4 q4 = *(const float4*)(xi + 16);
        float4 q5 = *(const float4*)(xi + 20);
        float4 q6 = *(const float4*)(xi + 24);
        float4 q7 = *(const float4*)(xi + 28);
        float4 q8 = *(const float4*)(xi + 32);
        float4 q9 = *(const float4*)(xi + 36);
        float xw[40];
        PUT4(q0, 0);  PUT4(q1, 4);  PUT4(q2, 8);  PUT4(q3, 12); PUT4(q4, 16);
        PUT4(q5, 20); PUT4(q6, 24); PUT4(q7, 28); PUT4(q8, 32); PUT4(q9, 36);
        float w0 = ws[(i * 5 + 0) * 65 + o];
        float w1 = ws[(i * 5 + 1) * 65 + o];
        float w2 = ws[(i * 5 + 2) * 65 + o];
        float w3 = ws[(i * 5 + 3) * 65 + o];
        float w4 = ws[(i * 5 + 4) * 65 + o];
        #pragma unroll
        for (int t = 0; t < 32; t++) {
            float a = acc[t];
            a = fmaf(xw[t + 2], w0, a);
            a = fmaf(xw[t + 3], w1, a);
            a = fmaf(xw[t + 4], w2, a);
            a = fmaf(xw[t + 5], w3, a);
            a = fmaf(xw[t + 6], w4, a);
            acc[t] = a;
        }
    }
    int bn = bn0 + bnL;
    float* ob = out + (size_t)bn * 2048 + o * 32;
    #pragma unroll
    for (int t = 0; t < 32; t++) {
        float xin = xr[o * XS_STRIDE + 4 + t];
        ob[t] = gelu_f(acc[t]) + xin;
    }
}

// ---------------- MLP1 split-K over nodes: 4g x 8o register tiles ----------------
#define ZS_STRIDE 65
#define MLP1_SMEM ((G_ * ZS_STRIDE + 64 * 256) * 4)
__global__ void k_mlp1(const float* __restrict__ xt, const float* __restrict__ W1) {
    extern __shared__ __align__(16) float sm[];
    float* zs  = sm;                       // [g][k], stride 65
    float* w1s = sm + G_ * ZS_STRIDE;      // [k][o]
    int n = blockIdx.x, tid = threadIdx.x;
    for (int i = tid; i < 8192; i += 256) {
        int b = i >> 11, c = (i >> 5) & 63, t = i & 31;
        zs[(b * 32 + t) * ZS_STRIDE + c] = xt[(((size_t)(b * N_ + n)) * 64 + c) * 32 + t];
    }
    for (int i = tid; i < 16384; i += 256)
        w1s[i] = W1[(size_t)n * 16384 + i];
    __syncthreads();
    int ow = tid & 31, gw = tid >> 5;
    int o0 = ow * 8;
    float* pb = d_part + (size_t)n * (G_ * 256);
    for (int pass = 0; pass < 4; pass++) {
        int g0 = pass * 32 + gw * 4;
        float acc[4][8] = {};
        #pragma unroll 4
        for (int k = 0; k < 64; k++) {
            float4 wa = *(const float4*)&w1s[k * 256 + o0];
            float4 wb = *(const float4*)&w1s[k * 256 + o0 + 4];
            float w[8] = {wa.x, wa.y, wa.z, wa.w, wb.x, wb.y, wb.z, wb.w};
            float z[4];
            #pragma unroll
            for (int j = 0; j < 4; j++) z[j] = zs[(g0 + j) * ZS_STRIDE + k];
            #pragma unroll
            for (int j = 0; j < 4; j++)
                #pragma unroll
                for (int q = 0; q < 8; q++)
                    acc[j][q] = fmaf(z[j], w[q], acc[j][q]);
        }
        #pragma unroll
        for (int j = 0; j < 4; j++) {
            *(float4*)&pb[(g0 + j) * 256 + o0]     = make_float4(acc[j][0], acc[j][1], acc[j][2], acc[j][3]);
            *(float4*)&pb[(g0 + j) * 256 + o0 + 4] = make_float4(acc[j][4], acc[j][5], acc[j][6], acc[j][7]);
        }
    }
}

// ---------------- reduce partials + bias + GELU + MLP2, fused ----------------
__global__ void k_redmlp2(const float* __restrict__ b1, const float* __restrict__ W2,
                          const float* __restrict__ b2, float* __restrict__ out) {
    __shared__ float hid[256];
    int g = blockIdx.x, o = threadIdx.x;
    float a0 = 0.f, a1 = 0.f;
    size_t base = (size_t)g * 256 + o;
    int nb = 0;
    for (; nb + 2 <= N_; nb += 2) {
        a0 += d_part[(size_t)nb * (G_ * 256) + base];
        a1 += d_part[(size_t)(nb + 1) * (G_ * 256) + base];
    }
    for (; nb < N_; nb++) a0 += d_part[(size_t)nb * (G_ * 256) + base];
    hid[o] = gelu_f(a0 + a1 + b1[o]);
    __syncthreads();
    if (o < 64) {
        float acc = b2[o];
        #pragma unroll 8
        for (int k = 0; k < 256; k++) acc = fmaf(hid[k], W2[k * 64 + o], acc);
        out[(size_t)g * 64 + o] = acc;
    }
}

// ---------------- host orchestration ----------------
extern "C" void kernel_launch(void* const* d_in, const int* in_sizes, int n_in,
                              void* d_out, int out_size) {
    float* out = (float*)d_out;

    cudaFuncSetAttribute(k_tconv, cudaFuncAttributeMaxDynamicSharedMemorySize, TCONV_SMEM);
    cudaFuncSetAttribute(k_mlp1,  cudaFuncAttributeMaxDynamicSharedMemorySize, MLP1_SMEM);

    // ---- stage all inputs into device globals (D2D async, graph-capturable) ----
    cudaMemcpyToSymbolAsync(d_xin,  d_in[0],  (size_t)GN * H_ * 4, 0, cudaMemcpyDeviceToDevice, 0);
    cudaMemcpyToSymbolAsync(d_eic,  d_in[1],  (size_t)2 * E_ * 4,  0, cudaMemcpyDeviceToDevice, 0);
    cudaMemcpyToSymbolAsync(d_ewc,  d_in[2],  (size_t)E_ * 4,      0, cudaMemcpyDeviceToDevice, 0);
    cudaMemcpyToSymbolAsync(d_Wg,   d_in[3],  (size_t)3 * 4096 * 4, 0, cudaMemcpyDeviceToDevice, 0);
    cudaMemcpyToSymbolAsync(d_bg,   d_in[4],  (size_t)3 * 64 * 4,   0, cudaMemcpyDeviceToDevice, 0);
    cudaMemcpyToSymbolAsync(d_Wa,   d_in[5],  (size_t)3 * 4096 * 4, 0, cudaMemcpyDeviceToDevice, 0);
    cudaMemcpyToSymbolAsync(d_asw,  d_in[6],  (size_t)3 * 64 * 4,   0, cudaMemcpyDeviceToDevice, 0);
    cudaMemcpyToSymbolAsync(d_adw,  d_in[7],  (size_t)3 * 64 * 4,   0, cudaMemcpyDeviceToDevice, 0);
    cudaMemcpyToSymbolAsync(d_ba,   d_in[8],  (size_t)3 * 64 * 4,   0, cudaMemcpyDeviceToDevice, 0);
    cudaMemcpyToSymbolAsync(d_Wt,   d_in[9],  (size_t)3 * 20480 * 4, 0, cudaMemcpyDeviceToDevice, 0);
    cudaMemcpyToSymbolAsync(d_bt,   d_in[10], (size_t)3 * 64 * 4,   0, cudaMemcpyDeviceToDevice, 0);
    cudaMemcpyToSymbolAsync(d_lngc, d_in[11], (size_t)3 * 64 * 4,   0, cudaMemcpyDeviceToDevice, 0);
    cudaMemcpyToSymbolAsync(d_lnbc, d_in[12], (size_t)3 * 64 * 4,   0, cudaMemcpyDeviceToDevice, 0);
    cudaMemcpyToSymbolAsync(d_W1c,  d_in[13], (size_t)NH * 256 * 4, 0, cudaMemcpyDeviceToDevice, 0);
    cudaMemcpyToSymbolAsync(d_b1c,  d_in[14], (size_t)256 * 4,      0, cudaMemcpyDeviceToDevice, 0);
    cudaMemcpyToSymbolAsync(d_W2c,  d_in[15], (size_t)256 * 64 * 4, 0, cudaMemcpyDeviceToDevice, 0);
    cudaMemcpyToSymbolAsync(d_b2c,  d_in[16], (size_t)64 * 4,       0, cudaMemcpyDeviceToDevice, 0);

    // device-global pointers (no host-side symbol lookup needed: use kernels' view)
    // We launch with pointers obtained from the device symbols via small helper casts.
    float* xin  = nullptr; cudaGetSymbolAddress((void**)&xin,  d_xin);
    float* Wg   = nullptr; cudaGetSymbolAddress((void**)&Wg,   d_Wg);
    float* bg   = nullptr; cudaGetSymbolAddress((void**)&bg,   d_bg);
    float* Wa   = nullptr; cudaGetSymbolAddress((void**)&Wa,   d_Wa);
    float* asw  = nullptr; cudaGetSymbolAddress((void**)&asw,  d_asw);
    float* adw  = nullptr; cudaGetSymbolAddress((void**)&adw,  d_adw);
    float* ba   = nullptr; cudaGetSymbolAddress((void**)&ba,   d_ba);
    float* Wt   = nullptr; cudaGetSymbolAddress((void**)&Wt,   d_Wt);
    float* bt   = nullptr; cudaGetSymbolAddress((void**)&bt,   d_bt);
    float* lng  = nullptr; cudaGetSymbolAddress((void**)&lng,  d_lngc);
    float* lnb  = nullptr; cudaGetSymbolAddress((void**)&lnb,  d_lnbc);
    float* W1   = nullptr; cudaGetSymbolAddress((void**)&W1,   d_W1c);
    float* b1   = nullptr; cudaGetSymbolAddress((void**)&b1,   d_b1c);
    float* W2   = nullptr; cudaGetSymbolAddress((void**)&W2,   d_W2c);
    float* b2   = nullptr; cudaGetSymbolAddress((void**)&b2,   d_b2c);
    float* hbuf = nullptr; cudaGetSymbolAddress((void**)&hbuf, d_h);
    float* bufA = nullptr; cudaGetSymbolAddress((void**)&bufA, d_bufA);
    float* bufB = nullptr; cudaGetSymbolAddress((void**)&bufB, d_bufB);
    float* xt0  = nullptr; cudaGetSymbolAddress((void**)&xt0,  d_xt0);
    float* xt1  = nullptr; cudaGetSymbolAddress((void**)&xt1,  d_xt1);

    k_prepA<<<1, CHUNK_>>>();
    k_prepB<<<(N_ + 3) / 4, 128>>>();
    k_prepC<<<(E2_ + 255) / 256, 256>>>();

    const float* hin = xin;
    for (int l = 0; l < 3; l++) {
        k_gemm64<<<GN / 64, 256>>>(hin, Wg + l * 4096, bufA, nullptr, nullptr, 0);
        k_gcn_agg<<<GN, 64>>>(bufA, bg + l * 64, bufB);
        k_gemm64<<<GN / 64, 256>>>(bufB, Wa + l * 4096, bufA, asw + l * 64, adw + l * 64, 1);
        k_gat<<<GN, 64>>>(bufA, ba + l * 64, lng + l * 64, lnb + l * 64, hin, hbuf);
        hin = hbuf;
    }

    k_tconv<<<(B_ * N_) / 4, 256, TCONV_SMEM>>>(hbuf, xt0, Wt + 0 * 20480, bt + 0 * 64, 1);
    k_tconv<<<(B_ * N_) / 4, 256, TCONV_SMEM>>>(xt0,  xt1, Wt + 1 * 20480, bt + 1 * 64, 0);
    k_tconv<<<(B_ * N_) / 4, 256, TCONV_SMEM>>>(xt1,  xt0, Wt + 2 * 20480, bt + 2 * 64, 0);

    k_mlp1<<<N_, 256, MLP1_SMEM>>>(xt0, W1);
    k_redmlp2<<<G_, 256>>>(b1, W2, b2, out);
}

// round 5
// speedup vs baseline: 15.5767x; 1.0020x over previous
#include <cuda_runtime.h>
#include <math.h>

#define B_   4
#define T_   32
#define N_   370
#define E_   11840
#define E2_  (E_ + N_)
#define G_   128
#define H_   64
#define GN   (G_ * N_)
#define NH   (N_ * H_)
#define CHUNK_ 512
#define DCAP 512

__device__ float d_xin[GN * H_];
__device__ int   d_eic[2 * E_];
__device__ float d_ewc[E_];
__device__ float d_Wg[3 * 4096];
__device__ float d_bg[3 * 64];
__device__ float d_Wa[3 * 4096];
__device__ float d_asw[3 * 64];
__device__ float d_adw[3 * 64];
__device__ float d_ba[3 * 64];
__device__ float d_Wt[3 * 20480];
__device__ float d_bt[3 * 64];
__device__ float d_lngc[3 * 64];
__device__ float d_lnbc[3 * 64];
__device__ float d_W1c[NH * 256];
__device__ float d_b1c[256];
__device__ float d_W2c[256 * 64];
__device__ float d_b2c[64];

__device__ float  d_h[GN * H_];
__device__ float  d_bufA[GN * H_];
__device__ int    d_csr_ptr[N_ + 1];
__device__ int    d_csr_eid[E2_];
__device__ int    d_csr_dst[E2_];
__device__ float  d_dis[N_];
__device__ float2 d_csr_sg[E2_];
__device__ int    d_cnt[CHUNK_ * N_];
__device__ float  d_xt0[B_ * N_ * H_ * T_];
__device__ float  d_xt1[B_ * N_ * H_ * T_];
__device__ float  d_part[N_ * G_ * 256];

__device__ __forceinline__ float gelu_f(float x) {
    return 0.5f * x * (1.0f + erff(x * 0.70710678118654752f));
}

// ---------------- prep ----------------
__global__ void k_prepA() {
    int t = threadIdx.x;
    const int* dsts = d_eic + E_;
    const int EC = (E_ + CHUNK_ - 1) / CHUNK_;
    int e0 = t * EC, e1 = min(e0 + EC, E_);
    __shared__ int ptr_s[N_ + 1];
    for (int i = t; i < CHUNK_ * N_; i += CHUNK_) d_cnt[i] = 0;
    __syncthreads();
    for (int e = e0; e < e1; e++) d_cnt[t * N_ + dsts[e]]++;
    __syncthreads();
    if (t < N_) {
        int run = 0;
        for (int c = 0; c < CHUNK_; c++) {
            int idx = c * N_ + t;
            int v = d_cnt[idx]; d_cnt[idx] = run; run += v;
        }
        ptr_s[t] = run + 1;
    }
    __syncthreads();
    if (t == 0) {
        int p = 0;
        for (int n = 0; n < N_; n++) { int v = ptr_s[n]; ptr_s[n] = p; p += v; }
        ptr_s[N_] = p;
    }
    __syncthreads();
    if (t <= N_) d_csr_ptr[t] = ptr_s[t];
    for (int e = e0; e < e1; e++) {
        int d = dsts[e];
        int pos = ptr_s[d] + d_cnt[t * N_ + d]++;
        d_csr_eid[pos] = e; d_csr_dst[pos] = d;
    }
    __syncthreads();
    if (t < N_) {
        int pos = ptr_s[t + 1] - 1;
        d_csr_eid[pos] = E_ + t; d_csr_dst[pos] = t;
    }
}

__global__ void k_prepB() {
    int n = blockIdx.x * 4 + (threadIdx.x >> 5);
    int lane = threadIdx.x & 31;
    if (n >= N_) return;
    int p0 = d_csr_ptr[n], p1 = d_csr_ptr[n + 1] - 1;
    float s = 0.0f;
    for (int p = p0 + lane; p < p1; p += 32) s += d_ewc[d_csr_eid[p]];
    #pragma unroll
    for (int off = 16; off; off >>= 1) s += __shfl_xor_sync(~0u, s, off);
    if (lane == 0) d_dis[n] = rsqrtf(s + 1.0f);
}

__global__ void k_prepC() {
    int pos = blockIdx.x * 256 + threadIdx.x;
    if (pos >= E2_) return;
    int e = d_csr_eid[pos], d = d_csr_dst[pos];
    float dd = d_dis[d];
    int s; float gn;
    if (e < E_) { s = d_eic[e]; gn = d_dis[s] * d_ewc[e] * dd; }
    else        { s = d;        gn = dd * dd; }
    d_csr_sg[pos] = make_float2(__int_as_float(s), gn);
}

// ------- in-block 370x64 @ 64x64 GEMM; W column held in registers -------
__device__ __forceinline__ void gemm_block(const float* __restrict__ in_s,
                                           const float* __restrict__ WsT,
                                           float* __restrict__ out_s, int tid) {
    int c = tid & 63, rb = tid >> 6;
    const float* wc = WsT + c * 68;
    float w[64];
    #pragma unroll
    for (int k = 0; k < 64; k += 4) *(float4*)&w[k] = *(const float4*)&wc[k];
    for (int r = rb; r < 185; r += 4) {
        int r2 = r + 185;
        float a0 = 0.f, a1 = 0.f, a2 = 0.f, a3 = 0.f;
        #pragma unroll
        for (int k = 0; k < 64; k += 4) {
            float4 h0 = *(const float4*)&in_s[r * 64 + k];
            float4 h1 = *(const float4*)&in_s[r2 * 64 + k];
            a0 = fmaf(h0.x, w[k], a0);     a1 = fmaf(h0.y, w[k + 1], a1);
            a0 = fmaf(h0.z, w[k + 2], a0); a1 = fmaf(h0.w, w[k + 3], a1);
            a2 = fmaf(h1.x, w[k], a2);     a3 = fmaf(h1.y, w[k + 1], a3);
            a2 = fmaf(h1.z, w[k + 2], a2); a3 = fmaf(h1.w, w[k + 3], a3);
        }
        out_s[r * 64 + c]  = a0 + a1;
        out_s[r2 * 64 + c] = a2 + a3;
    }
}

// ---------------- K1: GCN layer, one graph per block ----------------
#define GCN_SMEM ((2 * NH + 64 * 68) * 4)
__global__ void k_gcn(const float* __restrict__ hin, const float* __restrict__ Wg,
                      const float* __restrict__ bg, float* __restrict__ gout) {
    extern __shared__ __align__(16) float sm[];
    float* h_s  = sm;               // input h; reused as per-warp edge cache
    float* hw_s = sm + NH;
    float* WsT  = sm + 2 * NH;
    int g = blockIdx.x, tid = threadIdx.x;
    const float* hrow = hin + (size_t)g * NH;
    for (int i = tid * 4; i < NH; i += 1024)
        *(float4*)&h_s[i] = *(const float4*)&hrow[i];
    for (int i = tid; i < 4096; i += 256)
        WsT[(i & 63) * 68 + (i >> 6)] = Wg[i];
    __syncthreads();
    gemm_block(h_s, WsT, hw_s, tid);
    __syncthreads();

    int lane = tid & 31, w = tid >> 5;
    float2* scr = (float2*)(h_s + w * 2960);
    float bx = bg[2 * lane], by = bg[2 * lane + 1];
    for (int d = w; d < N_; d += 8) {
        int p0 = d_csr_ptr[d], deg = d_csr_ptr[d + 1] - p0;
        float2 acc = make_float2(0.f, 0.f);
        for (int j = lane; j < deg; j += 32) scr[j] = d_csr_sg[p0 + j];
        __syncwarp();
        int j = 0;
        for (; j + 2 <= deg; j += 2) {
            float2 s0 = scr[j], s1 = scr[j + 1];
            float2 v0 = *(const float2*)&hw_s[__float_as_int(s0.x) * 64 + 2 * lane];
            float2 v1 = *(const float2*)&hw_s[__float_as_int(s1.x) * 64 + 2 * lane];
            acc.x = fmaf(s0.y, v0.x, acc.x); acc.y = fmaf(s0.y, v0.y, acc.y);
            acc.x = fmaf(s1.y, v1.x, acc.x); acc.y = fmaf(s1.y, v1.y, acc.y);
        }
        if (j < deg) {
            float2 s0 = scr[j];
            float2 v0 = *(const float2*)&hw_s[__float_as_int(s0.x) * 64 + 2 * lane];
            acc.x = fmaf(s0.y, v0.x, acc.x); acc.y = fmaf(s0.y, v0.y, acc.y);
        }
        __syncwarp();
        *(float2*)&gout[((size_t)g * N_ + d) * 64 + 2 * lane] =
            make_float2(gelu_f(acc.x + bx), gelu_f(acc.y + by));
    }
}

// ---------------- K2: GAT + residual + LN, one graph per block ----------------
#define GAT2_SMEM ((2 * NH + 64 * 68 + N_ * 4) * 4)
__global__ void k_gat2(const float* __restrict__ gin, const float* __restrict__ Wa,
                       const float* __restrict__ attS, const float* __restrict__ attD,
                       const float* __restrict__ ba, const float* __restrict__ lng,
                       const float* __restrict__ lnb, const float* __restrict__ hin,
                       float* __restrict__ hout) {
    extern __shared__ __align__(16) float sm[];
    float* g_s    = sm;                     // input g; reused as per-warp scratch
    float* gh_s   = sm + NH;
    float* WsT    = sm + 2 * NH;
    float* asrc_s = sm + 2 * NH + 64 * 68;  // [N][4]
    int g = blockIdx.x, tid = threadIdx.x;
    const float* grow = gin + (size_t)g * NH;
    for (int i = tid * 4; i < NH; i += 1024)
        *(float4*)&g_s[i] = *(const float4*)&grow[i];
    for (int i = tid; i < 4096; i += 256)
        WsT[(i & 63) * 68 + (i >> 6)] = Wa[i];
    __syncthreads();
    gemm_block(g_s, WsT, gh_s, tid);
    __syncthreads();

    int lane = tid & 31, w = tid >> 5, hh = lane >> 3;
    float wsl = attS[lane], wsl2 = attS[lane + 32];
    float wdl = attD[lane], wdl2 = attD[lane + 32];
    for (int n = w; n < N_; n += 8) {
        float r1 = gh_s[n * 64 + lane] * wsl;
        float r2 = gh_s[n * 64 + 32 + lane] * wsl2;
        #pragma unroll
        for (int off = 8; off; off >>= 1) {
            r1 += __shfl_xor_sync(~0u, r1, off, 16);
            r2 += __shfl_xor_sync(~0u, r2, off, 16);
        }
        if (lane == 0)       { asrc_s[n * 4 + 0] = r1; asrc_s[n * 4 + 2] = r2; }
        else if (lane == 16) { asrc_s[n * 4 + 1] = r1; asrc_s[n * 4 + 3] = r2; }
    }
    __syncthreads();

    float* scrA = g_s + w * 2960;
    int*   scrS = (int*)(scrA + DCAP * 4);
    float bx  = ba[2 * lane],  by  = ba[2 * lane + 1];
    float gsx = lng[2 * lane], gsy = lng[2 * lane + 1];
    float gbx = lnb[2 * lane], gby = lnb[2 * lane + 1];

    for (int d = w; d < N_; d += 8) {
        float r1 = gh_s[d * 64 + lane] * wdl;
        float r2 = gh_s[d * 64 + 32 + lane] * wdl2;
        #pragma unroll
        for (int off = 8; off; off >>= 1) {
            r1 += __shfl_xor_sync(~0u, r1, off, 16);
            r2 += __shfl_xor_sync(~0u, r2, off, 16);
        }
        float h0 = __shfl_sync(~0u, r1, 0),  h1 = __shfl_sync(~0u, r1, 16);
        float h2 = __shfl_sync(~0u, r2, 0),  h3 = __shfl_sync(~0u, r2, 16);

        int p0 = d_csr_ptr[d], deg = d_csr_ptr[d + 1] - p0;
        float2 acc = make_float2(0.f, 0.f);
        float invh;
        if (deg <= DCAP) {
            float m0 = -1e30f, m1 = -1e30f, m2 = -1e30f, m3 = -1e30f;
            for (int j = lane; j < deg; j += 32) {
                float2 sgv = d_csr_sg[p0 + j];
                int s = __float_as_int(sgv.x);
                float4 av = *(const float4*)&asrc_s[s * 4];
                float a0 = av.x + h0, a1 = av.y + h1, a2 = av.z + h2, a3 = av.w + h3;
                a0 = fmaxf(a0, 0.2f * a0); a1 = fmaxf(a1, 0.2f * a1);
                a2 = fmaxf(a2, 0.2f * a2); a3 = fmaxf(a3, 0.2f * a3);
                scrA[j * 4 + 0] = a0; scrA[j * 4 + 1] = a1;
                scrA[j * 4 + 2] = a2; scrA[j * 4 + 3] = a3;
                scrS[j] = s;
                m0 = fmaxf(m0, a0); m1 = fmaxf(m1, a1);
                m2 = fmaxf(m2, a2); m3 = fmaxf(m3, a3);
            }
            #pragma unroll
            for (int off = 16; off; off >>= 1) {
                m0 = fmaxf(m0, __shfl_xor_sync(~0u, m0, off));
                m1 = fmaxf(m1, __shfl_xor_sync(~0u, m1, off));
                m2 = fmaxf(m2, __shfl_xor_sync(~0u, m2, off));
                m3 = fmaxf(m3, __shfl_xor_sync(~0u, m3, off));
            }
            __syncwarp();
            float d0 = 0.f, d1 = 0.f, d2 = 0.f, d3 = 0.f;
            for (int j = lane; j < deg; j += 32) {
                float e0 = __expf(scrA[j * 4 + 0] - m0);
                float e1 = __expf(scrA[j * 4 + 1] - m1);
                float e2 = __expf(scrA[j * 4 + 2] - m2);
                float e3 = __expf(scrA[j * 4 + 3] - m3);
                scrA[j * 4 + 0] = e0; scrA[j * 4 + 1] = e1;
                scrA[j * 4 + 2] = e2; scrA[j * 4 + 3] = e3;
                d0 += e0; d1 += e1; d2 += e2; d3 += e3;
            }
            #pragma unroll
            for (int off = 16; off; off >>= 1) {
                d0 += __shfl_xor_sync(~0u, d0, off);
                d1 += __shfl_xor_sync(~0u, d1, off);
                d2 += __shfl_xor_sync(~0u, d2, off);
                d3 += __shfl_xor_sync(~0u, d3, off);
            }
            invh = 1.0f / ((hh == 0) ? d0 : (hh == 1) ? d1 : (hh == 2) ? d2 : d3);
            __syncwarp();
            for (int j = 0; j < deg; j++) {
                float al = scrA[j * 4 + hh];
                float2 v = *(const float2*)&gh_s[scrS[j] * 64 + 2 * lane];
                acc.x = fmaf(al, v.x, acc.x); acc.y = fmaf(al, v.y, acc.y);
            }
        } else {                      // fallback: recompute from smem, 2-pass
            float adh = (hh == 0) ? h0 : (hh == 1) ? h1 : (hh == 2) ? h2 : h3;
            float m = -1e30f;
            for (int p = p0; p < p0 + deg; p++) {
                float a = asrc_s[__float_as_int(d_csr_sg[p].x) * 4 + hh] + adh;
                a = fmaxf(a, 0.2f * a);
                m = fmaxf(m, a);
            }
            float den = 0.f;
            for (int p = p0; p < p0 + deg; p++) {
                int s = __float_as_int(d_csr_sg[p].x);
                float a = asrc_s[s * 4 + hh] + adh;
                a = fmaxf(a, 0.2f * a);
                float e = __expf(a - m);
                den += e;
                float2 v = *(const float2*)&gh_s[s * 64 + 2 * lane];
                acc.x = fmaf(e, v.x, acc.x); acc.y = fmaf(e, v.y, acc.y);
            }
            invh = 1.0f / den;
        }
        float rx = acc.x * invh + bx + hin[((size_t)g * N_ + d) * 64 + 2 * lane];
        float ry = acc.y * invh + by + hin[((size_t)g * N_ + d) * 64 + 2 * lane + 1];
        float s1 = rx + ry, s2 = rx * rx + ry * ry;
        #pragma unroll
        for (int off = 16; off; off >>= 1) {
            s1 += __shfl_xor_sync(~0u, s1, off);
            s2 += __shfl_xor_sync(~0u, s2, off);
        }
        float mu = s1 * (1.0f / 64.0f);
        float var = fmaxf(s2 * (1.0f / 64.0f) - mu * mu, 0.0f);
        float inv = rsqrtf(var + 1e-5f);
        *(float2*)&hout[((size_t)g * N_ + d) * 64 + 2 * lane] =
            make_float2((rx - mu) * inv * gsx + gbx, (ry - mu) * inv * gsy + gby);
    }
}

// ---------------- temporal conv ----------------
#define WS_FLOATS (320 * 65)
#define XS_STRIDE 40
#define XS_PER_BN (64 * XS_STRIDE)
#define TCONV_SMEM ((WS_FLOATS + 4 * XS_PER_BN) * 4)
#define PUT4(q, idx) do { xw[idx] = q.x; xw[idx+1] = q.y; xw[idx+2] = q.z; xw[idx+3] = q.w; } while (0)

__global__ void k_tconv(const float* __restrict__ in, float* __restrict__ out,
                        const float* __restrict__ W, const float* __restrict__ bias,
                        int from_h) {
    extern __shared__ __align__(16) float sm[];
    float* ws = sm;
    float* xs = sm + WS_FLOATS;
    int tid = threadIdx.x;
    int bn0 = blockIdx.x * 4;
    for (int i = tid; i < 20480; i += 256) {
        int o = i / 320, r = i % 320;
        ws[r * 65 + o] = W[i];
    }
    for (int i = tid; i < 4 * XS_PER_BN; i += 256) xs[i] = 0.0f;
    __syncthreads();
    for (int idx = tid; idx < 4 * 2048; idx += 256) {
        int bnL = idx >> 11, r = idx & 2047, bn = bn0 + bnL;
        float v; int i2, tt;
        if (from_h) {
            tt = r >> 6; i2 = r & 63;
            int b = bn / N_, n = bn % N_;
            v = in[(((size_t)(b * 32 + tt) * N_) + n) * 64 + i2];
        } else {
            i2 = r >> 5; tt = r & 31;
            v = in[(size_t)bn * 2048 + r];
        }
        xs[bnL * XS_PER_BN + i2 * XS_STRIDE + 4 + tt] = v;
    }
    __syncthreads();
    int o = tid & 63, bnL = tid >> 6;
    const float* xr = xs + bnL * XS_PER_BN;
    float acc[32];
    float bo = bias[o];
    #pragma unroll
    for (int t = 0; t < 32; t++) acc[t] = bo;
    for (int i = 0; i < 64; i++) {
        const float* xi = xr + i * XS_STRIDE;
        float4 q0 = *(const float4*)(xi);      float4 q1 = *(const float4*)(xi + 4);
        float4 q2 = *(const float4*)(xi + 8);  float4 q3 = *(const float4*)(xi + 12);
        float4 q4 = *(const float4*)(xi + 16); float4 q5 = *(const float4*)(xi + 20);
        float4 q6 = *(const float4*)(xi + 24); float4 q7 = *(const float4*)(xi + 28);
        float4 q8 = *(const float4*)(xi + 32); float4 q9 = *(const float4*)(xi + 36);
        float xw[40];
        PUT4(q0, 0);  PUT4(q1, 4);  PUT4(q2, 8);  PUT4(q3, 12); PUT4(q4, 16);
        PUT4(q5, 20); PUT4(q6, 24); PUT4(q7, 28); PUT4(q8, 32); PUT4(q9, 36);
        float w0 = ws[(i * 5 + 0) * 65 + o];
        float w1 = ws[(i * 5 + 1) * 65 + o];
        float w2 = ws[(i * 5 + 2) * 65 + o];
        float w3 = ws[(i * 5 + 3) * 65 + o];
        float w4 = ws[(i * 5 + 4) * 65 + o];
        #pragma unroll
        for (int t = 0; t < 32; t++) {
            float a = acc[t];
            a = fmaf(xw[t + 2], w0, a); a = fmaf(xw[t + 3], w1, a);
            a = fmaf(xw[t + 4], w2, a); a = fmaf(xw[t + 5], w3, a);
            a = fmaf(xw[t + 6], w4, a);
            acc[t] = a;
        }
    }
    int bn = bn0 + bnL;
    float* ob = out + (size_t)bn * 2048 + o * 32;
    #pragma unroll
    for (int t = 0; t < 32; t++)
        ob[t] = gelu_f(acc[t]) + xr[o * XS_STRIDE + 4 + t];
}

// ---------------- MLP1 split-K ----------------
#define ZS_STRIDE 65
#define MLP1_SMEM ((G_ * ZS_STRIDE + 64 * 256) * 4)
__global__ void k_mlp1(const float* __restrict__ xt, const float* __restrict__ W1) {
    extern __shared__ __align__(16) float sm[];
    float* zs  = sm;
    float* w1s = sm + G_ * ZS_STRIDE;
    int n = blockIdx.x, tid = threadIdx.x;
    for (int i = tid; i < 8192; i += 256) {
        int b = i >> 11, c = (i >> 5) & 63, t = i & 31;
        zs[(b * 32 + t) * ZS_STRIDE + c] = xt[(((size_t)(b * N_ + n)) * 64 + c) * 32 + t];
    }
    for (int i = tid; i < 16384; i += 256)
        w1s[i] = W1[(size_t)n * 16384 + i];
    __syncthreads();
    int ow = tid & 31, gw = tid >> 5, o0 = ow * 8;
    float* pb = d_part + (size_t)n * (G_ * 256);
    for (int pass = 0; pass < 4; pass++) {
        int g0 = pass * 32 + gw * 4;
        float acc[4][8] = {};
        #pragma unroll 4
        for (int k = 0; k < 64; k++) {
            float4 wa = *(const float4*)&w1s[k * 256 + o0];
            float4 wb = *(const float4*)&w1s[k * 256 + o0 + 4];
            float wv[8] = {wa.x, wa.y, wa.z, wa.w, wb.x, wb.y, wb.z, wb.w};
            float z[4];
            #pragma unroll
            for (int j = 0; j < 4; j++) z[j] = zs[(g0 + j) * ZS_STRIDE + k];
            #pragma unroll
            for (int j = 0; j < 4; j++)
                #pragma unroll
                for (int q = 0; q < 8; q++)
                    acc[j][q] = fmaf(z[j], wv[q], acc[j][q]);
        }
        #pragma unroll
        for (int j = 0; j < 4; j++) {
            *(float4*)&pb[(g0 + j) * 256 + o0]     = make_float4(acc[j][0], acc[j][1], acc[j][2], acc[j][3]);
            *(float4*)&pb[(g0 + j) * 256 + o0 + 4] = make_float4(acc[j][4], acc[j][5], acc[j][6], acc[j][7]);
        }
    }
}

__global__ void k_redmlp2(const float* __restrict__ b1, const float* __restrict__ W2,
                          const float* __restrict__ b2, float* __restrict__ out) {
    __shared__ float hid[256];
    int g = blockIdx.x, o = threadIdx.x;
    float a0 = 0.f, a1 = 0.f;
    size_t base = (size_t)g * 256 + o;
    int nb = 0;
    for (; nb + 2 <= N_; nb += 2) {
        a0 += d_part[(size_t)nb * (G_ * 256) + base];
        a1 += d_part[(size_t)(nb + 1) * (G_ * 256) + base];
    }
    for (; nb < N_; nb++) a0 += d_part[(size_t)nb * (G_ * 256) + base];
    hid[o] = gelu_f(a0 + a1 + b1[o]);
    __syncthreads();
    if (o < 64) {
        float acc = b2[o];
        #pragma unroll 8
        for (int k = 0; k < 256; k++) acc = fmaf(hid[k], W2[k * 64 + o], acc);
        out[(size_t)g * 64 + o] = acc;
    }
}

extern "C" void kernel_launch(void* const* d_in, const int* in_sizes, int n_in,
                              void* d_out, int out_size) {
    float* out = (float*)d_out;
    cudaFuncSetAttribute(k_gcn,   cudaFuncAttributeMaxDynamicSharedMemorySize, GCN_SMEM);
    cudaFuncSetAttribute(k_gat2,  cudaFuncAttributeMaxDynamicSharedMemorySize, GAT2_SMEM);
    cudaFuncSetAttribute(k_tconv, cudaFuncAttributeMaxDynamicSharedMemorySize, TCONV_SMEM);
    cudaFuncSetAttribute(k_mlp1,  cudaFuncAttributeMaxDynamicSharedMemorySize, MLP1_SMEM);

    cudaMemcpyToSymbolAsync(d_xin,  d_in[0],  (size_t)GN * H_ * 4, 0, cudaMemcpyDeviceToDevice, 0);
    cudaMemcpyToSymbolAsync(d_eic,  d_in[1],  (size_t)2 * E_ * 4,  0, cudaMemcpyDeviceToDevice, 0);
    cudaMemcpyToSymbolAsync(d_ewc,  d_in[2],  (size_t)E_ * 4,      0, cudaMemcpyDeviceToDevice, 0);
    cudaMemcpyToSymbolAsync(d_Wg,   d_in[3],  12288 * 4, 0, cudaMemcpyDeviceToDevice, 0);
    cudaMemcpyToSymbolAsync(d_bg,   d_in[4],  192 * 4,   0, cudaMemcpyDeviceToDevice, 0);
    cudaMemcpyToSymbolAsync(d_Wa,   d_in[5],  12288 * 4, 0, cudaMemcpyDeviceToDevice, 0);
    cudaMemcpyToSymbolAsync(d_asw,  d_in[6],  192 * 4,   0, cudaMemcpyDeviceToDevice, 0);
    cudaMemcpyToSymbolAsync(d_adw,  d_in[7],  192 * 4,   0, cudaMemcpyDeviceToDevice, 0);
    cudaMemcpyToSymbolAsync(d_ba,   d_in[8],  192 * 4,   0, cudaMemcpyDeviceToDevice, 0);
    cudaMemcpyToSymbolAsync(d_Wt,   d_in[9],  61440 * 4, 0, cudaMemcpyDeviceToDevice, 0);
    cudaMemcpyToSymbolAsync(d_bt,   d_in[10], 192 * 4,   0, cudaMemcpyDeviceToDevice, 0);
    cudaMemcpyToSymbolAsync(d_lngc, d_in[11], 192 * 4,   0, cudaMemcpyDeviceToDevice, 0);
    cudaMemcpyToSymbolAsync(d_lnbc, d_in[12], 192 * 4,   0, cudaMemcpyDeviceToDevice, 0);
    cudaMemcpyToSymbolAsync(d_W1c,  d_in[13], (size_t)NH * 256 * 4, 0, cudaMemcpyDeviceToDevice, 0);
    cudaMemcpyToSymbolAsync(d_b1c,  d_in[14], 256 * 4,   0, cudaMemcpyDeviceToDevice, 0);
    cudaMemcpyToSymbolAsync(d_W2c,  d_in[15], 16384 * 4, 0, cudaMemcpyDeviceToDevice, 0);
    cudaMemcpyToSymbolAsync(d_b2c,  d_in[16], 64 * 4,    0, cudaMemcpyDeviceToDevice, 0);

    float *xin, *Wg, *bg, *Wa, *asw, *adw, *ba, *Wt, *bt, *lng, *lnb, *W1, *b1, *W2, *b2;
    float *hbuf, *bufA, *xt0, *xt1;
    cudaGetSymbolAddress((void**)&xin,  d_xin);
    cudaGetSymbolAddress((void**)&Wg,   d_Wg);
    cudaGetSymbolAddress((void**)&bg,   d_bg);
    cudaGetSymbolAddress((void**)&Wa,   d_Wa);
    cudaGetSymbolAddress((void**)&asw,  d_asw);
    cudaGetSymbolAddress((void**)&adw,  d_adw);
    cudaGetSymbolAddress((void**)&ba,   d_ba);
    cudaGetSymbolAddress((void**)&Wt,   d_Wt);
    cudaGetSymbolAddress((void**)&bt,   d_bt);
    cudaGetSymbolAddress((void**)&lng,  d_lngc);
    cudaGetSymbolAddress((void**)&lnb,  d_lnbc);
    cudaGetSymbolAddress((void**)&W1,   d_W1c);
    cudaGetSymbolAddress((void**)&b1,   d_b1c);
    cudaGetSymbolAddress((void**)&W2,   d_W2c);
    cudaGetSymbolAddress((void**)&b2,   d_b2c);
    cudaGetSymbolAddress((void**)&hbuf, d_h);
    cudaGetSymbolAddress((void**)&bufA, d_bufA);
    cudaGetSymbolAddress((void**)&xt0,  d_xt0);
    cudaGetSymbolAddress((void**)&xt1,  d_xt1);

    k_prepA<<<1, CHUNK_>>>();
    k_prepB<<<(N_ + 3) / 4, 128>>>();
    k_prepC<<<(E2_ + 255) / 256, 256>>>();

    const float* hin = xin;
    for (int l = 0; l < 3; l++) {
        k_gcn<<<G_, 256, GCN_SMEM>>>(hin, Wg + l * 4096, bg + l * 64, bufA);
        k_gat2<<<G_, 256, GAT2_SMEM>>>(bufA, Wa + l * 4096, asw + l * 64, adw + l * 64,
                                       ba + l * 64, lng + l * 64, lnb + l * 64, hin, hbuf);
        hin = hbuf;
    }

    k_tconv<<<(B_ * N_) / 4, 256, TCONV_SMEM>>>(hbuf, xt0, Wt, bt, 1);
    k_tconv<<<(B_ * N_) / 4, 256, TCONV_SMEM>>>(xt0,  xt1, Wt + 20480, bt + 64, 0);
    k_tconv<<<(B_ * N_) / 4, 256, TCONV_SMEM>>>(xt1,  xt0, Wt + 40960, bt + 128, 0);

    k_mlp1<<<N_, 256, MLP1_SMEM>>>(xt0, W1);
    k_redmlp2<<<G_, 256>>>(b1, W2, b2, out);
}

// round 6
// speedup vs baseline: 19.0617x; 1.2237x over previous
#include <cuda_runtime.h>
#include <math.h>

#define B_   4
#define T_   32
#define N_   370
#define E_   11840
#define E2_  (E_ + N_)
#define G_   128
#define H_   64
#define GN   (G_ * N_)
#define NH   (N_ * H_)
#define CHUNK_ 512
#define DCAP 256

__device__ float d_xin[GN * H_];
__device__ int   d_eic[2 * E_];
__device__ float d_ewc[E_];
__device__ float d_Wg[3 * 4096];
__device__ float d_bg[3 * 64];
__device__ float d_Wa[3 * 4096];
__device__ float d_asw[3 * 64];
__device__ float d_adw[3 * 64];
__device__ float d_ba[3 * 64];
__device__ float d_Wt[3 * 20480];
__device__ float d_bt[3 * 64];
__device__ float d_lngc[3 * 64];
__device__ float d_lnbc[3 * 64];
__device__ float d_W1c[NH * 256];
__device__ float d_b1c[256];
__device__ float d_W2c[256 * 64];
__device__ float d_b2c[64];

__device__ float  d_h[GN * H_];
__device__ float  d_bufA[GN * H_];
__device__ int    d_csr_ptr[N_ + 1];
__device__ int    d_csr_eid[E2_];
__device__ int    d_csr_dst[E2_];
__device__ float  d_dis[N_];
__device__ float2 d_csr_sg[E2_];
__device__ int    d_cnt[CHUNK_ * N_];
__device__ float  d_xt0[B_ * N_ * H_ * T_];
__device__ float  d_xt1[B_ * N_ * H_ * T_];
__device__ float  d_part[N_ * G_ * 256];

__device__ __forceinline__ float gelu_f(float x) {
    return 0.5f * x * (1.0f + erff(x * 0.70710678118654752f));
}

// ---------------- staging kernels (consolidate small copies) ----------------
__global__ void k_stageA(const int* ei, const float* ew, const float* Wg,
                         const float* bg, const float* Wa, const float* asw,
                         const float* adw, const float* ba, const float* lng,
                         const float* lnb) {
    int i0 = blockIdx.x * 256 + threadIdx.x, st = gridDim.x * 256;
    for (int i = i0; i < 2 * E_; i += st) d_eic[i] = ei[i];
    for (int i = i0; i < E_;    i += st) d_ewc[i] = ew[i];
    for (int i = i0; i < 12288; i += st) { d_Wg[i] = Wg[i]; d_Wa[i] = Wa[i]; }
    for (int i = i0; i < 192;   i += st) {
        d_bg[i] = bg[i]; d_asw[i] = asw[i]; d_adw[i] = adw[i];
        d_ba[i] = ba[i]; d_lngc[i] = lng[i]; d_lnbc[i] = lnb[i];
    }
}
__global__ void k_stageB(const float* Wt, const float* bt, const float* b1,
                         const float* W2, const float* b2) {
    int i0 = blockIdx.x * 256 + threadIdx.x, st = gridDim.x * 256;
    for (int i = i0; i < 61440; i += st) d_Wt[i] = Wt[i];
    for (int i = i0; i < 192;   i += st) d_bt[i] = bt[i];
    for (int i = i0; i < 256;   i += st) d_b1c[i] = b1[i];
    for (int i = i0; i < 16384; i += st) d_W2c[i] = W2[i];
    for (int i = i0; i < 64;    i += st) d_b2c[i] = b2[i];
}

// ---------------- prep ----------------
__global__ void k_prepA() {
    int t = threadIdx.x;
    const int* dsts = d_eic + E_;
    const int EC = (E_ + CHUNK_ - 1) / CHUNK_;
    int e0 = t * EC, e1 = min(e0 + EC, E_);
    __shared__ int ptr_s[N_ + 1];
    for (int i = t; i < CHUNK_ * N_; i += CHUNK_) d_cnt[i] = 0;
    __syncthreads();
    for (int e = e0; e < e1; e++) d_cnt[t * N_ + dsts[e]]++;
    __syncthreads();
    if (t < N_) {
        int run = 0;
        for (int c = 0; c < CHUNK_; c++) {
            int idx = c * N_ + t;
            int v = d_cnt[idx]; d_cnt[idx] = run; run += v;
        }
        ptr_s[t] = run + 1;
    }
    __syncthreads();
    if (t == 0) {
        int p = 0;
        for (int n = 0; n < N_; n++) { int v = ptr_s[n]; ptr_s[n] = p; p += v; }
        ptr_s[N_] = p;
    }
    __syncthreads();
    if (t <= N_) d_csr_ptr[t] = ptr_s[t];
    for (int e = e0; e < e1; e++) {
        int d = dsts[e];
        int pos = ptr_s[d] + d_cnt[t * N_ + d]++;
        d_csr_eid[pos] = e; d_csr_dst[pos] = d;
    }
    __syncthreads();
    if (t < N_) {
        int pos = ptr_s[t + 1] - 1;
        d_csr_eid[pos] = E_ + t; d_csr_dst[pos] = t;
    }
}

__global__ void k_prepB() {
    int n = blockIdx.x * 4 + (threadIdx.x >> 5);
    int lane = threadIdx.x & 31;
    if (n >= N_) return;
    int p0 = d_csr_ptr[n], p1 = d_csr_ptr[n + 1] - 1;
    float s = 0.0f;
    for (int p = p0 + lane; p < p1; p += 32) s += d_ewc[d_csr_eid[p]];
    #pragma unroll
    for (int off = 16; off; off >>= 1) s += __shfl_xor_sync(~0u, s, off);
    if (lane == 0) d_dis[n] = rsqrtf(s + 1.0f);
}

__global__ void k_prepC() {
    int pos = blockIdx.x * 256 + threadIdx.x;
    if (pos >= E2_) return;
    int e = d_csr_eid[pos], d = d_csr_dst[pos];
    float dd = d_dis[d];
    int s; float gn;
    if (e < E_) { s = d_eic[e]; gn = d_dis[s] * d_ewc[e] * dd; }
    else        { s = d;        gn = dd * dd; }
    d_csr_sg[pos] = make_float2(__int_as_float(s), gn);
}

// ------- in-block 370x64 @ 64x64 GEMM (512 threads), W column in registers -------
__device__ __forceinline__ void gemm_block(const float* __restrict__ in_s,
                                           const float* __restrict__ WsT,
                                           float* __restrict__ out_s, int tid) {
    int c = tid & 63, rb = tid >> 6;          // rb in 0..7
    const float* wc = WsT + c * 68;
    float w[64];
    #pragma unroll
    for (int k = 0; k < 64; k += 4) *(float4*)&w[k] = *(const float4*)&wc[k];
    for (int r = rb; r < 185; r += 8) {
        int r2 = r + 185;
        float a0 = 0.f, a1 = 0.f, a2 = 0.f, a3 = 0.f;
        #pragma unroll
        for (int k = 0; k < 64; k += 4) {
            float4 h0 = *(const float4*)&in_s[r * 64 + k];
            float4 h1 = *(const float4*)&in_s[r2 * 64 + k];
            a0 = fmaf(h0.x, w[k], a0);     a1 = fmaf(h0.y, w[k + 1], a1);
            a0 = fmaf(h0.z, w[k + 2], a0); a1 = fmaf(h0.w, w[k + 3], a1);
            a2 = fmaf(h1.x, w[k], a2);     a3 = fmaf(h1.y, w[k + 1], a3);
            a2 = fmaf(h1.z, w[k + 2], a2); a3 = fmaf(h1.w, w[k + 3], a3);
        }
        out_s[r * 64 + c]  = a0 + a1;
        out_s[r2 * 64 + c] = a2 + a3;
    }
}

// ---------------- K1: GCN layer, one graph per block, 512 threads ----------------
#define GCN_SMEM ((2 * NH + 64 * 68) * 4)
__global__ void k_gcn(const float* __restrict__ hin, const float* __restrict__ Wg,
                      const float* __restrict__ bg, float* __restrict__ gout) {
    extern __shared__ __align__(16) float sm[];
    float* h_s  = sm;                  // reused as per-warp edge cache
    float* hw_s = sm + NH;
    float* WsT  = sm + 2 * NH;
    int g = blockIdx.x, tid = threadIdx.x;
    const float* hrow = hin + (size_t)g * NH;
    for (int i = tid * 4; i < NH; i += 2048)
        *(float4*)&h_s[i] = *(const float4*)&hrow[i];
    for (int i = tid; i < 4096; i += 512)
        WsT[(i & 63) * 68 + (i >> 6)] = Wg[i];
    __syncthreads();
    gemm_block(h_s, WsT, hw_s, tid);
    __syncthreads();

    int lane = tid & 31, w = tid >> 5;       // 16 warps
    float2* scr = (float2*)(h_s + w * 1480); // 740 float2 per warp
    float bx = bg[2 * lane], by = bg[2 * lane + 1];
    for (int d = w; d < N_; d += 16) {
        int p0 = d_csr_ptr[d], deg = d_csr_ptr[d + 1] - p0;
        float2 acc = make_float2(0.f, 0.f);
        for (int j = lane; j < deg; j += 32) scr[j] = d_csr_sg[p0 + j];
        __syncwarp();
        int j = 0;
        for (; j + 2 <= deg; j += 2) {
            float2 s0 = scr[j], s1 = scr[j + 1];
            float2 v0 = *(const float2*)&hw_s[__float_as_int(s0.x) * 64 + 2 * lane];
            float2 v1 = *(const float2*)&hw_s[__float_as_int(s1.x) * 64 + 2 * lane];
            acc.x = fmaf(s0.y, v0.x, acc.x); acc.y = fmaf(s0.y, v0.y, acc.y);
            acc.x = fmaf(s1.y, v1.x, acc.x); acc.y = fmaf(s1.y, v1.y, acc.y);
        }
        if (j < deg) {
            float2 s0 = scr[j];
            float2 v0 = *(const float2*)&hw_s[__float_as_int(s0.x) * 64 + 2 * lane];
            acc.x = fmaf(s0.y, v0.x, acc.x); acc.y = fmaf(s0.y, v0.y, acc.y);
        }
        __syncwarp();
        *(float2*)&gout[((size_t)g * N_ + d) * 64 + 2 * lane] =
            make_float2(gelu_f(acc.x + bx), gelu_f(acc.y + by));
    }
}

// ---------------- K2: GAT + residual + LN, one graph per block, 512 threads ----------------
#define GAT2_SMEM ((2 * NH + 64 * 68 + N_ * 4) * 4)
__global__ void k_gat2(const float* __restrict__ gin, const float* __restrict__ Wa,
                       const float* __restrict__ attS, const float* __restrict__ attD,
                       const float* __restrict__ ba, const float* __restrict__ lng,
                       const float* __restrict__ lnb, const float* __restrict__ hin,
                       float* __restrict__ hout) {
    extern __shared__ __align__(16) float sm[];
    float* g_s    = sm;                     // reused as per-warp scratch
    float* gh_s   = sm + NH;
    float* WsT    = sm + 2 * NH;
    float* asrc_s = sm + 2 * NH + 64 * 68;  // [N][4]
    int g = blockIdx.x, tid = threadIdx.x;
    const float* grow = gin + (size_t)g * NH;
    for (int i = tid * 4; i < NH; i += 2048)
        *(float4*)&g_s[i] = *(const float4*)&grow[i];
    for (int i = tid; i < 4096; i += 512)
        WsT[(i & 63) * 68 + (i >> 6)] = Wa[i];
    __syncthreads();
    gemm_block(g_s, WsT, gh_s, tid);
    __syncthreads();

    int lane = tid & 31, w = tid >> 5, hh = lane >> 3;
    float wsl = attS[lane], wsl2 = attS[lane + 32];
    float wdl = attD[lane], wdl2 = attD[lane + 32];
    for (int n = w; n < N_; n += 16) {
        float r1 = gh_s[n * 64 + lane] * wsl;
        float r2 = gh_s[n * 64 + 32 + lane] * wsl2;
        #pragma unroll
        for (int off = 8; off; off >>= 1) {
            r1 += __shfl_xor_sync(~0u, r1, off, 16);
            r2 += __shfl_xor_sync(~0u, r2, off, 16);
        }
        if (lane == 0)       { asrc_s[n * 4 + 0] = r1; asrc_s[n * 4 + 2] = r2; }
        else if (lane == 16) { asrc_s[n * 4 + 1] = r1; asrc_s[n * 4 + 3] = r2; }
    }
    __syncthreads();

    float* scrA = g_s + w * 1480;           // 4*DCAP floats + DCAP ints = 1280
    int*   scrS = (int*)(scrA + DCAP * 4);
    float bx  = ba[2 * lane],  by  = ba[2 * lane + 1];
    float gsx = lng[2 * lane], gsy = lng[2 * lane + 1];
    float gbx = lnb[2 * lane], gby = lnb[2 * lane + 1];

    for (int d = w; d < N_; d += 16) {
        float r1 = gh_s[d * 64 + lane] * wdl;
        float r2 = gh_s[d * 64 + 32 + lane] * wdl2;
        #pragma unroll
        for (int off = 8; off; off >>= 1) {
            r1 += __shfl_xor_sync(~0u, r1, off, 16);
            r2 += __shfl_xor_sync(~0u, r2, off, 16);
        }
        float h0 = __shfl_sync(~0u, r1, 0),  h1 = __shfl_sync(~0u, r1, 16);
        float h2 = __shfl_sync(~0u, r2, 0),  h3 = __shfl_sync(~0u, r2, 16);

        int p0 = d_csr_ptr[d], deg = d_csr_ptr[d + 1] - p0;
        float2 acc = make_float2(0.f, 0.f);
        float invh;
        if (deg <= DCAP) {
            float m0 = -1e30f, m1 = -1e30f, m2 = -1e30f, m3 = -1e30f;
            for (int j = lane; j < deg; j += 32) {
                float2 sgv = d_csr_sg[p0 + j];
                int s = __float_as_int(sgv.x);
                float4 av = *(const float4*)&asrc_s[s * 4];
                float a0 = av.x + h0, a1 = av.y + h1, a2 = av.z + h2, a3 = av.w + h3;
                a0 = fmaxf(a0, 0.2f * a0); a1 = fmaxf(a1, 0.2f * a1);
                a2 = fmaxf(a2, 0.2f * a2); a3 = fmaxf(a3, 0.2f * a3);
                scrA[j * 4 + 0] = a0; scrA[j * 4 + 1] = a1;
                scrA[j * 4 + 2] = a2; scrA[j * 4 + 3] = a3;
                scrS[j] = s;
                m0 = fmaxf(m0, a0); m1 = fmaxf(m1, a1);
                m2 = fmaxf(m2, a2); m3 = fmaxf(m3, a3);
            }
            #pragma unroll
            for (int off = 16; off; off >>= 1) {
                m0 = fmaxf(m0, __shfl_xor_sync(~0u, m0, off));
                m1 = fmaxf(m1, __shfl_xor_sync(~0u, m1, off));
                m2 = fmaxf(m2, __shfl_xor_sync(~0u, m2, off));
                m3 = fmaxf(m3, __shfl_xor_sync(~0u, m3, off));
            }
            __syncwarp();
            float d0 = 0.f, d1 = 0.f, d2 = 0.f, d3 = 0.f;
            for (int j = lane; j < deg; j += 32) {
                float e0 = __expf(scrA[j * 4 + 0] - m0);
                float e1 = __expf(scrA[j * 4 + 1] - m1);
                float e2 = __expf(scrA[j * 4 + 2] - m2);
                float e3 = __expf(scrA[j * 4 + 3] - m3);
                scrA[j * 4 + 0] = e0; scrA[j * 4 + 1] = e1;
                scrA[j * 4 + 2] = e2; scrA[j * 4 + 3] = e3;
                d0 += e0; d1 += e1; d2 += e2; d3 += e3;
            }
            #pragma unroll
            for (int off = 16; off; off >>= 1) {
                d0 += __shfl_xor_sync(~0u, d0, off);
                d1 += __shfl_xor_sync(~0u, d1, off);
                d2 += __shfl_xor_sync(~0u, d2, off);
                d3 += __shfl_xor_sync(~0u, d3, off);
            }
            invh = 1.0f / ((hh == 0) ? d0 : (hh == 1) ? d1 : (hh == 2) ? d2 : d3);
            __syncwarp();
            for (int j = 0; j < deg; j++) {
                float al = scrA[j * 4 + hh];
                float2 v = *(const float2*)&gh_s[scrS[j] * 64 + 2 * lane];
                acc.x = fmaf(al, v.x, acc.x); acc.y = fmaf(al, v.y, acc.y);
            }
        } else {
            float adh = (hh == 0) ? h0 : (hh == 1) ? h1 : (hh == 2) ? h2 : h3;
            float m = -1e30f;
            for (int p = p0; p < p0 + deg; p++) {
                float a = asrc_s[__float_as_int(d_csr_sg[p].x) * 4 + hh] + adh;
                a = fmaxf(a, 0.2f * a);
                m = fmaxf(m, a);
            }
            float den = 0.f;
            for (int p = p0; p < p0 + deg; p++) {
                int s = __float_as_int(d_csr_sg[p].x);
                float a = asrc_s[s * 4 + hh] + adh;
                a = fmaxf(a, 0.2f * a);
                float e = __expf(a - m);
                den += e;
                float2 v = *(const float2*)&gh_s[s * 64 + 2 * lane];
                acc.x = fmaf(e, v.x, acc.x); acc.y = fmaf(e, v.y, acc.y);
            }
            invh = 1.0f / den;
        }
        float rx = acc.x * invh + bx + hin[((size_t)g * N_ + d) * 64 + 2 * lane];
        float ry = acc.y * invh + by + hin[((size_t)g * N_ + d) * 64 + 2 * lane + 1];
        float s1 = rx + ry, s2 = rx * rx + ry * ry;
        #pragma unroll
        for (int off = 16; off; off >>= 1) {
            s1 += __shfl_xor_sync(~0u, s1, off);
            s2 += __shfl_xor_sync(~0u, s2, off);
        }
        float mu = s1 * (1.0f / 64.0f);
        float var = fmaxf(s2 * (1.0f / 64.0f) - mu * mu, 0.0f);
        float inv = rsqrtf(var + 1e-5f);
        *(float2*)&hout[((size_t)g * N_ + d) * 64 + 2 * lane] =
            make_float2((rx - mu) * inv * gsx + gbx, (ry - mu) * inv * gsy + gby);
    }
}

// ---------------- temporal conv ----------------
#define WS_FLOATS (320 * 65)
#define XS_STRIDE 40
#define XS_PER_BN (64 * XS_STRIDE)
#define TCONV_SMEM ((WS_FLOATS + 4 * XS_PER_BN) * 4)
#define PUT4(q, idx) do { xw[idx] = q.x; xw[idx+1] = q.y; xw[idx+2] = q.z; xw[idx+3] = q.w; } while (0)

__global__ void k_tconv(const float* __restrict__ in, float* __restrict__ out,
                        const float* __restrict__ W, const float* __restrict__ bias,
                        int from_h) {
    extern __shared__ __align__(16) float sm[];
    float* ws = sm;
    float* xs = sm + WS_FLOATS;
    int tid = threadIdx.x;
    int bn0 = blockIdx.x * 4;
    for (int i = tid; i < 20480; i += 256) {
        int o = i / 320, r = i % 320;
        ws[r * 65 + o] = W[i];
    }
    for (int i = tid; i < 4 * XS_PER_BN; i += 256) xs[i] = 0.0f;
    __syncthreads();
    for (int idx = tid; idx < 4 * 2048; idx += 256) {
        int bnL = idx >> 11, r = idx & 2047, bn = bn0 + bnL;
        float v; int i2, tt;
        if (from_h) {
            tt = r >> 6; i2 = r & 63;
            int b = bn / N_, n = bn % N_;
            v = in[(((size_t)(b * 32 + tt) * N_) + n) * 64 + i2];
        } else {
            i2 = r >> 5; tt = r & 31;
            v = in[(size_t)bn * 2048 + r];
        }
        xs[bnL * XS_PER_BN + i2 * XS_STRIDE + 4 + tt] = v;
    }
    __syncthreads();
    int o = tid & 63, bnL = tid >> 6;
    const float* xr = xs + bnL * XS_PER_BN;
    float acc[32];
    float bo = bias[o];
    #pragma unroll
    for (int t = 0; t < 32; t++) acc[t] = bo;
    for (int i = 0; i < 64; i++) {
        const float* xi = xr + i * XS_STRIDE;
        float4 q0 = *(const float4*)(xi);      float4 q1 = *(const float4*)(xi + 4);
        float4 q2 = *(const float4*)(xi + 8);  float4 q3 = *(const float4*)(xi + 12);
        float4 q4 = *(const float4*)(xi + 16); float4 q5 = *(const float4*)(xi + 20);
        float4 q6 = *(const float4*)(xi + 24); float4 q7 = *(const float4*)(xi + 28);
        float4 q8 = *(const float4*)(xi + 32); float4 q9 = *(const float4*)(xi + 36);
        float xw[40];
        PUT4(q0, 0);  PUT4(q1, 4);  PUT4(q2, 8);  PUT4(q3, 12); PUT4(q4, 16);
        PUT4(q5, 20); PUT4(q6, 24); PUT4(q7, 28); PUT4(q8, 32); PUT4(q9, 36);
        float w0 = ws[(i * 5 + 0) * 65 + o];
        float w1 = ws[(i * 5 + 1) * 65 + o];
        float w2 = ws[(i * 5 + 2) * 65 + o];
        float w3 = ws[(i * 5 + 3) * 65 + o];
        float w4 = ws[(i * 5 + 4) * 65 + o];
        #pragma unroll
        for (int t = 0; t < 32; t++) {
            float a = acc[t];
            a = fmaf(xw[t + 2], w0, a); a = fmaf(xw[t + 3], w1, a);
            a = fmaf(xw[t + 4], w2, a); a = fmaf(xw[t + 5], w3, a);
            a = fmaf(xw[t + 6], w4, a);
            acc[t] = a;
        }
    }
    int bn = bn0 + bnL;
    float* ob = out + (size_t)bn * 2048 + o * 32;
    #pragma unroll
    for (int t = 0; t < 32; t++)
        ob[t] = gelu_f(acc[t]) + xr[o * XS_STRIDE + 4 + t];
}

// ---------------- MLP1 split-K ----------------
#define ZS_STRIDE 65
#define MLP1_SMEM ((G_ * ZS_STRIDE + 64 * 256) * 4)
__global__ void k_mlp1(const float* __restrict__ xt, const float* __restrict__ W1) {
    extern __shared__ __align__(16) float sm[];
    float* zs  = sm;
    float* w1s = sm + G_ * ZS_STRIDE;
    int n = blockIdx.x, tid = threadIdx.x;
    for (int i = tid; i < 8192; i += 256) {
        int b = i >> 11, c = (i >> 5) & 63, t = i & 31;
        zs[(b * 32 + t) * ZS_STRIDE + c] = xt[(((size_t)(b * N_ + n)) * 64 + c) * 32 + t];
    }
    for (int i = tid; i < 16384; i += 256)
        w1s[i] = W1[(size_t)n * 16384 + i];
    __syncthreads();
    int ow = tid & 31, gw = tid >> 5, o0 = ow * 8;
    float* pb = d_part + (size_t)n * (G_ * 256);
    for (int pass = 0; pass < 4; pass++) {
        int g0 = pass * 32 + gw * 4;
        float acc[4][8] = {};
        #pragma unroll 4
        for (int k = 0; k < 64; k++) {
            float4 wa = *(const float4*)&w1s[k * 256 + o0];
            float4 wb = *(const float4*)&w1s[k * 256 + o0 + 4];
            float wv[8] = {wa.x, wa.y, wa.z, wa.w, wb.x, wb.y, wb.z, wb.w};
            float z[4];
            #pragma unroll
            for (int j = 0; j < 4; j++) z[j] = zs[(g0 + j) * ZS_STRIDE + k];
            #pragma unroll
            for (int j = 0; j < 4; j++)
                #pragma unroll
                for (int q = 0; q < 8; q++)
                    acc[j][q] = fmaf(z[j], wv[q], acc[j][q]);
        }
        #pragma unroll
        for (int j = 0; j < 4; j++) {
            *(float4*)&pb[(g0 + j) * 256 + o0]     = make_float4(acc[j][0], acc[j][1], acc[j][2], acc[j][3]);
            *(float4*)&pb[(g0 + j) * 256 + o0 + 4] = make_float4(acc[j][4], acc[j][5], acc[j][6], acc[j][7]);
        }
    }
}

__global__ void k_redmlp2(const float* __restrict__ b1, const float* __restrict__ W2,
                          const float* __restrict__ b2, float* __restrict__ out) {
    __shared__ float hid[256];
    int g = blockIdx.x, o = threadIdx.x;
    float a0 = 0.f, a1 = 0.f;
    size_t base = (size_t)g * 256 + o;
    int nb = 0;
    for (; nb + 2 <= N_; nb += 2) {
        a0 += d_part[(size_t)nb * (G_ * 256) + base];
        a1 += d_part[(size_t)(nb + 1) * (G_ * 256) + base];
    }
    for (; nb < N_; nb++) a0 += d_part[(size_t)nb * (G_ * 256) + base];
    hid[o] = gelu_f(a0 + a1 + b1[o]);
    __syncthreads();
    if (o < 64) {
        float acc = b2[o];
        #pragma unroll 8
        for (int k = 0; k < 256; k++) acc = fmaf(hid[k], W2[k * 64 + o], acc);
        out[(size_t)g * 64 + o] = acc;
    }
}

extern "C" void kernel_launch(void* const* d_in, const int* in_sizes, int n_in,
                              void* d_out, int out_size) {
    float* out = (float*)d_out;
    static cudaStream_t s2 = nullptr;
    static cudaEvent_t evFork = nullptr, evX = nullptr, evJoin = nullptr;
    if (s2 == nullptr) {
        cudaStreamCreateWithFlags(&s2, cudaStreamNonBlocking);
        cudaEventCreateWithFlags(&evFork, cudaEventDisableTiming);
        cudaEventCreateWithFlags(&evX,    cudaEventDisableTiming);
        cudaEventCreateWithFlags(&evJoin, cudaEventDisableTiming);
        cudaFuncSetAttribute(k_gcn,   cudaFuncAttributeMaxDynamicSharedMemorySize, GCN_SMEM);
        cudaFuncSetAttribute(k_gat2,  cudaFuncAttributeMaxDynamicSharedMemorySize, GAT2_SMEM);
        cudaFuncSetAttribute(k_tconv, cudaFuncAttributeMaxDynamicSharedMemorySize, TCONV_SMEM);
        cudaFuncSetAttribute(k_mlp1,  cudaFuncAttributeMaxDynamicSharedMemorySize, MLP1_SMEM);
    }

    // fork side stream: big copies (x, W1) + late-needed params
    cudaEventRecord(evFork, 0);
    cudaStreamWaitEvent(s2, evFork, 0);
    cudaMemcpyToSymbolAsync(d_xin, d_in[0], (size_t)GN * H_ * 4, 0, cudaMemcpyDeviceToDevice, s2);
    cudaEventRecord(evX, s2);
    cudaMemcpyToSymbolAsync(d_W1c, d_in[13], (size_t)NH * 256 * 4, 0, cudaMemcpyDeviceToDevice, s2);
    k_stageB<<<48, 256, 0, s2>>>((const float*)d_in[9], (const float*)d_in[10],
                                 (const float*)d_in[14], (const float*)d_in[15],
                                 (const float*)d_in[16]);
    cudaEventRecord(evJoin, s2);

    // main stream: small layer params + CSR prep (overlaps x copy)
    k_stageA<<<64, 256>>>((const int*)d_in[1], (const float*)d_in[2],
                          (const float*)d_in[3], (const float*)d_in[4],
                          (const float*)d_in[5], (const float*)d_in[6],
                          (const float*)d_in[7], (const float*)d_in[8],
                          (const float*)d_in[11], (const float*)d_in[12]);
    k_prepA<<<1, CHUNK_>>>();
    k_prepB<<<(N_ + 3) / 4, 128>>>();
    k_prepC<<<(E2_ + 255) / 256, 256>>>();
    cudaStreamWaitEvent(0, evX, 0);

    float *xin, *Wg, *bg, *Wa, *asw, *adw, *ba, *Wt, *bt, *lng, *lnb, *W1, *b1, *W2, *b2;
    float *hbuf, *bufA, *xt0, *xt1;
    cudaGetSymbolAddress((void**)&xin,  d_xin);
    cudaGetSymbolAddress((void**)&Wg,   d_Wg);
    cudaGetSymbolAddress((void**)&bg,   d_bg);
    cudaGetSymbolAddress((void**)&Wa,   d_Wa);
    cudaGetSymbolAddress((void**)&asw,  d_asw);
    cudaGetSymbolAddress((void**)&adw,  d_adw);
    cudaGetSymbolAddress((void**)&ba,   d_ba);
    cudaGetSymbolAddress((void**)&Wt,   d_Wt);
    cudaGetSymbolAddress((void**)&bt,   d_bt);
    cudaGetSymbolAddress((void**)&lng,  d_lngc);
    cudaGetSymbolAddress((void**)&lnb,  d_lnbc);
    cudaGetSymbolAddress((void**)&W1,   d_W1c);
    cudaGetSymbolAddress((void**)&b1,   d_b1c);
    cudaGetSymbolAddress((void**)&W2,   d_W2c);
    cudaGetSymbolAddress((void**)&b2,   d_b2c);
    cudaGetSymbolAddress((void**)&hbuf, d_h);
    cudaGetSymbolAddress((void**)&bufA, d_bufA);
    cudaGetSymbolAddress((void**)&xt0,  d_xt0);
    cudaGetSymbolAddress((void**)&xt1,  d_xt1);

    const float* hin = xin;
    for (int l = 0; l < 3; l++) {
        k_gcn<<<G_, 512, GCN_SMEM>>>(hin, Wg + l * 4096, bg + l * 64, bufA);
        k_gat2<<<G_, 512, GAT2_SMEM>>>(bufA, Wa + l * 4096, asw + l * 64, adw + l * 64,
                                       ba + l * 64, lng + l * 64, lnb + l * 64, hin, hbuf);
        hin = hbuf;
    }

    cudaStreamWaitEvent(0, evJoin, 0);
    k_tconv<<<(B_ * N_) / 4, 256, TCONV_SMEM>>>(hbuf, xt0, Wt, bt, 1);
    k_tconv<<<(B_ * N_) / 4, 256, TCONV_SMEM>>>(xt0,  xt1, Wt + 20480, bt + 64, 0);
    k_tconv<<<(B_ * N_) / 4, 256, TCONV_SMEM>>>(xt1,  xt0, Wt + 40960, bt + 128, 0);

    k_mlp1<<<N_, 256, MLP1_SMEM>>>(xt0, W1);
    k_redmlp2<<<G_, 256>>>(b1, W2, b2, out);
}